// round 13
// baseline (speedup 1.0000x reference)
#include <cuda_runtime.h>
#include <cuda_bf16.h>
#include <stdint.h>
#include <math.h>

#define L_SEQ 2048
#define BATCH 2
#define EMB   1024
#define NH    16
#define DQKh  128
#define QKD   2048
#define DVh   64
#define NROWS 4096

typedef __nv_bfloat16 bf16;

// ---------------- scratch (static device globals; no allocation) -------------
__device__ bf16 g_inq_hi[(size_t)NROWS*EMB];
__device__ bf16 g_inq_lo[(size_t)NROWS*EMB];
__device__ bf16 g_ink_hi[(size_t)NROWS*EMB];
__device__ bf16 g_ink_lo[(size_t)NROWS*EMB];
__device__ bf16 g_inv_hi[(size_t)NROWS*EMB];
__device__ bf16 g_inv_lo[(size_t)NROWS*EMB];
__device__ bf16 g_wq_hi[(size_t)QKD*EMB];
__device__ bf16 g_wq_lo[(size_t)QKD*EMB];
__device__ bf16 g_wk_hi[(size_t)QKD*EMB];
__device__ bf16 g_wk_lo[(size_t)QKD*EMB];
__device__ bf16 g_wv_hi[(size_t)EMB*EMB];
__device__ bf16 g_wv_lo[(size_t)EMB*EMB];
__device__ bf16 g_wo_hi[(size_t)EMB*EMB];
__device__ bf16 g_wo_lo[(size_t)EMB*EMB];
__device__ bf16 g_q_hi[(size_t)BATCH*NH*L_SEQ*DQKh];
__device__ bf16 g_q_lo[(size_t)BATCH*NH*L_SEQ*DQKh];
__device__ bf16 g_k_hi[(size_t)BATCH*NH*L_SEQ*DQKh];   // pre-masked, perm-d
__device__ bf16 g_k_lo[(size_t)BATCH*NH*L_SEQ*DQKh];   // pre-masked, perm-d
__device__ bf16 g_v_hi[(size_t)BATCH*NH*L_SEQ*DVh];
__device__ bf16 g_v_lo[(size_t)BATCH*NH*L_SEQ*DVh];
__device__ uint32_t g_vp_hi[(size_t)BATCH*NH*(L_SEQ/2)*DVh]; // paired (s,s+1)
__device__ uint32_t g_vp_lo[(size_t)BATCH*NH*(L_SEQ/2)*DVh];
__device__ float g_kg[(size_t)BATCH*NH*32*DQKh];       // unmasked global k (perm-d)
__device__ bf16 g_at_hi[(size_t)NROWS*EMB];            // perm-d
__device__ bf16 g_at_lo[(size_t)NROWS*EMB];            // perm-d
__device__ float g_corr[(size_t)BATCH*NH*L_SEQ*32];
__device__ int   g_ws[NH*L_SEQ];

// ---------------- asm helpers -------------------------------------------------
__device__ __forceinline__ void mma_bf16(float c[4], const uint32_t a[4],
                                         uint32_t b0, uint32_t b1) {
    asm volatile(
        "mma.sync.aligned.m16n8k16.row.col.f32.bf16.bf16.f32 "
        "{%0,%1,%2,%3},{%4,%5,%6,%7},{%8,%9},{%0,%1,%2,%3};"
        : "+f"(c[0]), "+f"(c[1]), "+f"(c[2]), "+f"(c[3])
        : "r"(a[0]), "r"(a[1]), "r"(a[2]), "r"(a[3]), "r"(b0), "r"(b1));
}

#define CP16(dst, src) \
    asm volatile("cp.async.cg.shared.global [%0], [%1], 16;" \
                 :: "r"(dst), "l"(src))
#define CP_COMMIT() asm volatile("cp.async.commit_group;")
#define CP_WAIT1()  asm volatile("cp.async.wait_group 1;")
#define CP_WAIT0()  asm volatile("cp.async.wait_group 0;")

// within-16 k-permutation (even d): pairs (2i,2i+1)->(4i,4i+1), (2i+8,2i+9)->(4i+2,4i+3)
__device__ __forceinline__ int permd(int d) {
    int c = d & 15;
    int p = (c < 8) ? (2 * c) : (2 * c - 14);
    return (d & ~15) + p;
}

__device__ __forceinline__ uint32_t mpair(uint32_t v, int d, int ws) {
    uint32_t m = 0;
    if ((unsigned)(d - ws) < 32u)     m |= 0x0000FFFFu;
    if ((unsigned)(d + 1 - ws) < 32u) m |= 0xFFFF0000u;
    return v & m;
}

__device__ __forceinline__ void split_pack(float x, float y,
                                           uint32_t& hi, uint32_t& lo) {
    __nv_bfloat16 hx = __float2bfloat16(x), hy = __float2bfloat16(y);
    __nv_bfloat162 ph; ph.x = hx; ph.y = hy;
    hi = *(uint32_t*)&ph;
    __nv_bfloat162 pl;
    pl.x = __float2bfloat16(x - __bfloat162float(hx));
    pl.y = __float2bfloat16(y - __bfloat162float(hy));
    lo = *(uint32_t*)&pl;
}

__device__ __forceinline__ void store_hl(bf16* hip, bf16* lop, size_t idx,
                                         float v0, float v1) {
    __nv_bfloat16 h0 = __float2bfloat16(v0), h1 = __float2bfloat16(v1);
    __nv_bfloat162 hh; hh.x = h0; hh.y = h1;
    *(__nv_bfloat162*)(hip + idx) = hh;
    __nv_bfloat162 ll;
    ll.x = __float2bfloat16(v0 - __bfloat162float(h0));
    ll.y = __float2bfloat16(v1 - __bfloat162float(h1));
    *(__nv_bfloat162*)(lop + idx) = ll;
}

// ---------------- setup kernels ----------------------------------------------
__global__ void build_ws_kernel() {
    int idx = blockIdx.x * blockDim.x + threadIdx.x;
    if (idx >= NH * L_SEQ) return;
    int h = idx / L_SEQ, l = idx % L_SEQ;
    int ws = 0;
    if (h > 0) {
        int rn = 96 / h + 1;
        int i = l / rn, m = l % rn;
        int mm = (i & 1) ? (rn - 1 - m) : m;
        ws = mm * h;
    }
    g_ws[idx] = ws;
}

// fused conversion of all 7 tensors; writes PERMUTED k-order (within 16-chunks)
struct CvtArgs { const float* src[7]; bf16* hi[7]; bf16* lo[7]; };

__global__ void __launch_bounds__(256) cvt_all(CvtArgs a) {
    int t = blockIdx.x * 256 + threadIdx.x;   // float4 unit index
    int seg, j;
    if      (t < 1048576) { seg = 0; j = t; }
    else if (t < 2097152) { seg = 1; j = t - 1048576; }
    else if (t < 3145728) { seg = 2; j = t - 2097152; }
    else if (t < 3670016) { seg = 3; j = t - 3145728; }
    else if (t < 4194304) { seg = 4; j = t - 3670016; }
    else if (t < 4456448) { seg = 5; j = t - 4194304; }
    else                  { seg = 6; j = t - 4456448; }
    float4 x = ((const float4*)a.src[seg])[j];
    uint32_t h0, l0, h1, l1;
    split_pack(x.x, x.y, h0, l0);
    split_pack(x.z, x.w, h1, l1);
    // permuted u32 slots: group of 16 elems = 8 u32s
    int g2 = (j >> 2) << 3;
    int c4 = (j & 3) << 2;                    // 0,4,8,12
    int i0 = (c4 < 8) ? c4 : (c4 - 7);        // p(c4)/2
    int i1 = (c4 + 2 < 8) ? (c4 + 2) : (c4 - 5);
    ((uint32_t*)a.hi[seg])[g2 + i0] = h0;
    ((uint32_t*)a.hi[seg])[g2 + i1] = h1;
    ((uint32_t*)a.lo[seg])[g2 + i0] = l0;
    ((uint32_t*)a.lo[seg])[g2 + i1] = l1;
}

// pack V planes [y][s][d] -> paired u32 [y][s2][d] = (v[2s2][d], v[2s2+1][d])
__global__ void __launch_bounds__(256) vpack_kernel(
    const bf16* __restrict__ vhi, const bf16* __restrict__ vlo,
    uint32_t* __restrict__ phi, uint32_t* __restrict__ plo)
{
    int i = blockIdx.x * 256 + threadIdx.x;   // 8-d unit
    int db = i & 7;
    int s2 = (i >> 3) & 1023;
    int y  = i >> 13;
    size_t src = ((size_t)(y * L_SEQ + 2 * s2)) * DVh + db * 8;
    size_t dst = ((size_t)(y * (L_SEQ / 2) + s2)) * DVh + db * 8;

    uint4 ah = *(const uint4*)(vhi + src);
    uint4 bh = *(const uint4*)(vhi + src + DVh);
    ((uint4*)(phi + dst))[0] = make_uint4(
        __byte_perm(ah.x, bh.x, 0x5410), __byte_perm(ah.x, bh.x, 0x7632),
        __byte_perm(ah.y, bh.y, 0x5410), __byte_perm(ah.y, bh.y, 0x7632));
    ((uint4*)(phi + dst))[1] = make_uint4(
        __byte_perm(ah.z, bh.z, 0x5410), __byte_perm(ah.z, bh.z, 0x7632),
        __byte_perm(ah.w, bh.w, 0x5410), __byte_perm(ah.w, bh.w, 0x7632));

    uint4 al = *(const uint4*)(vlo + src);
    uint4 bl = *(const uint4*)(vlo + src + DVh);
    ((uint4*)(plo + dst))[0] = make_uint4(
        __byte_perm(al.x, bl.x, 0x5410), __byte_perm(al.x, bl.x, 0x7632),
        __byte_perm(al.y, bl.y, 0x5410), __byte_perm(al.y, bl.y, 0x7632));
    ((uint4*)(plo + dst))[1] = make_uint4(
        __byte_perm(al.z, bl.z, 0x5410), __byte_perm(al.z, bl.z, 0x7632),
        __byte_perm(al.w, bl.w, 0x5410), __byte_perm(al.w, bl.w, 0x7632));
}

// ---------------- GEMM core: 128x128, 4 warps 64x64, cp.async x3, LDS64 ------
// smem stride 16 elems (no pad; permuted k makes frag loads contiguous uint2)
// MODE 0: fp32 out [M,N]
// MODE 1: relu*scale -> bf16 hi/lo planes [(b h) l d_perm], D=128  (q)
// MODE 2: linear     -> bf16 hi/lo planes [(b h) l d], D=64        (v)
// MODE 3: relu -> MASKED perm-d bf16 planes D=128 (k) + perm-d fp32 g_kg rows
#define GSTAGE 16384

template <int MODE>
__device__ __forceinline__ void gemm_body(
    const bf16* __restrict__ Ahi, const bf16* __restrict__ Alo,
    const bf16* __restrict__ Whi, const bf16* __restrict__ Wlo,
    const float* __restrict__ bias,
    float* __restrict__ Cf, bf16* __restrict__ Ohi, bf16* __restrict__ Olo,
    float* __restrict__ kg, int N, int K, float scale)
{
    extern __shared__ bf16 gsm[];
    int tid = threadIdx.x;
    int wid = tid >> 5, lane = tid & 31;
    int r = lane >> 2, qc = lane & 3;
    int warp_m = (wid >> 1) * 64, warp_n = (wid & 1) * 64;
    int m0 = blockIdx.y * 128, n0 = blockIdx.x * 128;

    const bf16* pAh = Ahi + (size_t)m0 * K;
    const bf16* pAl = Alo + (size_t)m0 * K;
    const bf16* pWh = Whi + (size_t)n0 * K;
    const bf16* pWl = Wlo + (size_t)n0 * K;

    uint32_t sb = (uint32_t)__cvta_generic_to_shared(gsm);

    auto load_stage = [&](int kt, uint32_t sbase) {
        #pragma unroll
        for (int i = 0; i < 2; i++) {
            int c = tid + i * 128;
            int row = c >> 1, half = (c & 1) * 8;
            uint32_t dst = sbase + (uint32_t)(row * 32 + (c & 1) * 16);
            size_t off = (size_t)row * K + kt + half;
            CP16(dst,         pAh + off);
            CP16(dst +  4096, pAl + off);
            CP16(dst +  8192, pWh + off);
            CP16(dst + 12288, pWl + off);
        }
    };

    // 3-stage ring: prologue fills stages 0 and 1
    load_stage(0, sb);
    CP_COMMIT();
    load_stage(16, sb + GSTAGE);
    CP_COMMIT();

    float acc[4][8][4] = {};
    int T = K >> 4;
    int cur = 0, pf = 2;
    for (int t = 0; t < T; t++) {
        if (t < T - 1) { CP_WAIT1(); } else { CP_WAIT0(); }
        __syncthreads();
        if (t + 2 < T) { load_stage((t + 2) << 4, sb + pf * GSTAGE); CP_COMMIT(); }

        bf16* sAh = gsm + cur * (GSTAGE / 2);
        bf16* sAl = sAh + 2048;
        bf16* sWh = sAl + 2048;
        bf16* sWl = sWh + 2048;

        uint32_t af[2][4][4];
        #pragma unroll
        for (int mt = 0; mt < 4; mt++) {
            int row = warp_m + mt * 16 + r;
            uint2 aH0 = *(const uint2*)&sAh[row * 16 + 4 * qc];
            uint2 aH1 = *(const uint2*)&sAh[(row + 8) * 16 + 4 * qc];
            uint2 aL0 = *(const uint2*)&sAl[row * 16 + 4 * qc];
            uint2 aL1 = *(const uint2*)&sAl[(row + 8) * 16 + 4 * qc];
            af[0][mt][0] = aH0.x; af[0][mt][1] = aH1.x;
            af[0][mt][2] = aH0.y; af[0][mt][3] = aH1.y;
            af[1][mt][0] = aL0.x; af[1][mt][1] = aL1.x;
            af[1][mt][2] = aL0.y; af[1][mt][3] = aL1.y;
        }
        #pragma unroll
        for (int nt = 0; nt < 8; nt++) {
            int wrow = warp_n + nt * 8 + r;
            uint2 bH = *(const uint2*)&sWh[wrow * 16 + 4 * qc];
            uint2 bL = *(const uint2*)&sWl[wrow * 16 + 4 * qc];
            #pragma unroll
            for (int mt = 0; mt < 4; mt++) {
                mma_bf16(acc[mt][nt], af[0][mt], bH.x, bH.y);
                mma_bf16(acc[mt][nt], af[0][mt], bL.x, bL.y);
                mma_bf16(acc[mt][nt], af[1][mt], bH.x, bH.y);
            }
        }
        cur = (cur == 2) ? 0 : cur + 1;
        pf  = (pf == 2)  ? 0 : pf + 1;
    }

    #pragma unroll
    for (int mt = 0; mt < 4; mt++) {
        #pragma unroll
        for (int nt = 0; nt < 8; nt++) {
            int row0 = m0 + warp_m + mt * 16 + r;
            int row1 = row0 + 8;
            int col  = n0 + warp_n + nt * 8 + 2 * qc;
            float b0f = bias[col], b1f = bias[col + 1];
            float v00 = acc[mt][nt][0] + b0f, v01 = acc[mt][nt][1] + b1f;
            float v10 = acc[mt][nt][2] + b0f, v11 = acc[mt][nt][3] + b1f;
            if (MODE == 1 || MODE == 3) {
                v00 = fmaxf(v00, 0.f) * scale; v01 = fmaxf(v01, 0.f) * scale;
                v10 = fmaxf(v10, 0.f) * scale; v11 = fmaxf(v11, 0.f) * scale;
            }
            if (MODE == 0) {
                *(float2*)(Cf + (size_t)row0 * N + col) = make_float2(v00, v01);
                *(float2*)(Cf + (size_t)row1 * N + col) = make_float2(v10, v11);
            } else if (MODE == 1) {
                int h = col >> 7, dp = permd(col & 127);
                store_hl(Ohi, Olo,
                    ((size_t)((row0 & 1) * NH + h) * L_SEQ + (row0 >> 1)) * DQKh + dp,
                    v00, v01);
                store_hl(Ohi, Olo,
                    ((size_t)((row1 & 1) * NH + h) * L_SEQ + (row1 >> 1)) * DQKh + dp,
                    v10, v11);
            } else if (MODE == 2) {
                int h = col >> 6, d = col & 63;
                store_hl(Ohi, Olo,
                    ((size_t)((row0 & 1) * NH + h) * L_SEQ + (row0 >> 1)) * DVh + d,
                    v00, v01);
                store_hl(Ohi, Olo,
                    ((size_t)((row1 & 1) * NH + h) * L_SEQ + (row1 >> 1)) * DVh + d,
                    v10, v11);
            } else {
                int h = col >> 7, d = col & 127;
                int dp = permd(d);
                int l0i = row0 >> 1, b0i = row0 & 1;
                int l1i = row1 >> 1, b1i = row1 & 1;
                if (l0i < 16 || l0i >= L_SEQ - 16) {
                    int j = (l0i < 16) ? l0i : (l0i - (L_SEQ - 32));
                    size_t o = ((size_t)(b0i * NH + h) * 32 + j) * DQKh + dp;
                    kg[o] = v00; kg[o + 1] = v01;
                }
                if (l1i < 16 || l1i >= L_SEQ - 16) {
                    int j = (l1i < 16) ? l1i : (l1i - (L_SEQ - 32));
                    size_t o = ((size_t)(b1i * NH + h) * 32 + j) * DQKh + dp;
                    kg[o] = v10; kg[o + 1] = v11;
                }
                if (h != 0) {
                    int ws0 = g_ws[h * L_SEQ + l0i];
                    int ws1 = g_ws[h * L_SEQ + l1i];
                    if ((unsigned)(d - ws0) >= 32u)     v00 = 0.f;
                    if ((unsigned)(d + 1 - ws0) >= 32u) v01 = 0.f;
                    if ((unsigned)(d - ws1) >= 32u)     v10 = 0.f;
                    if ((unsigned)(d + 1 - ws1) >= 32u) v11 = 0.f;
                }
                store_hl(Ohi, Olo,
                    ((size_t)(b0i * NH + h) * L_SEQ + l0i) * DQKh + dp, v00, v01);
                store_hl(Ohi, Olo,
                    ((size_t)(b1i * NH + h) * L_SEQ + l1i) * DQKh + dp, v10, v11);
            }
        }
    }
}

// fused q/k/v projection: z=0 -> q (MODE1), z=1 -> k (MODE3), z=2 -> v (MODE2)
struct ProjArgs {
    const bf16 *aq_hi, *aq_lo, *ak_hi, *ak_lo, *av_hi, *av_lo;
    const bf16 *wq_hi, *wq_lo, *wk_hi, *wk_lo, *wv_hi, *wv_lo;
    const float *bq, *bk, *bv;
    bf16 *q_hi, *q_lo, *k_hi, *k_lo, *v_hi, *v_lo;
    float* kg;
    float scale;
};

__global__ void __launch_bounds__(128) proj_gemm(ProjArgs p) {
    int z = blockIdx.z;
    if (z == 0) {
        gemm_body<1>(p.aq_hi, p.aq_lo, p.wq_hi, p.wq_lo, p.bq,
                     nullptr, p.q_hi, p.q_lo, nullptr, QKD, EMB, p.scale);
    } else if (z == 1) {
        gemm_body<3>(p.ak_hi, p.ak_lo, p.wk_hi, p.wk_lo, p.bk,
                     nullptr, p.k_hi, p.k_lo, p.kg, QKD, EMB, 1.0f);
    } else {
        if (blockIdx.x >= EMB / 128) return;
        gemm_body<2>(p.av_hi, p.av_lo, p.wv_hi, p.wv_lo, p.bv,
                     nullptr, p.v_hi, p.v_lo, nullptr, EMB, EMB, 1.0f);
    }
}

__global__ void __launch_bounds__(128) out_gemm(
    const bf16* __restrict__ Ahi, const bf16* __restrict__ Alo,
    const bf16* __restrict__ Whi, const bf16* __restrict__ Wlo,
    const float* __restrict__ bias, float* __restrict__ Cf)
{
    gemm_body<0>(Ahi, Alo, Whi, Wlo, bias, Cf, nullptr, nullptr, nullptr,
                 EMB, EMB, 1.0f);
}

// ---------------- global-key correction: corr[y,l,j] = q[l]·kg[j] ------------
// q and kg share the SAME d-permutation -> dot product invariant.
__global__ void __launch_bounds__(256) corr_kernel(
    const bf16* __restrict__ qhi, const bf16* __restrict__ qlo,
    const float* __restrict__ kg, float* __restrict__ corr)
{
    __shared__ float sKg[32][128];
    int tid = threadIdx.x;
    int y = blockIdx.y;
    int l0 = blockIdx.x * 128;

    for (int i = tid; i < 32 * 128; i += 256)
        sKg[i >> 7][i & 127] = kg[(size_t)y * 32 * 128 + i];
    __syncthreads();

    int l = l0 + (tid >> 1);
    int jb = (tid & 1) * 16;
    float acc[16] = {};
    size_t qb = ((size_t)y * L_SEQ + l) * DQKh;
    for (int d = 0; d < 128; d += 2) {
        uint32_t ph = *(const uint32_t*)(qhi + qb + d);
        uint32_t pl = *(const uint32_t*)(qlo + qb + d);
        __nv_bfloat162 h2 = *(__nv_bfloat162*)&ph;
        __nv_bfloat162 l2 = *(__nv_bfloat162*)&pl;
        float q0 = __bfloat162float(h2.x) + __bfloat162float(l2.x);
        float q1 = __bfloat162float(h2.y) + __bfloat162float(l2.y);
        #pragma unroll
        for (int j = 0; j < 16; j++)
            acc[j] += q0 * sKg[jb + j][d] + q1 * sKg[jb + j][d + 1];
    }
    float* cp = corr + ((size_t)y * L_SEQ + l) * 32 + jb;
    #pragma unroll
    for (int j = 0; j < 16; j++) cp[j] = acc[j];
}

// ---------------- attention: 128 thr, 64 q-rows, cp.async x2, LDS64 ----------
// K smem row stride 144 elems (72 u32-units = 8 mod 32 -> LDS64 conflict-free)
#define AT_KHI 0
#define AT_KLO 18432
#define AT_VHI 36864
#define AT_VLO 46080
#define AT_STAGE 55296

__global__ void __launch_bounds__(128) attn_mma(
    const bf16* __restrict__ qhi, const bf16* __restrict__ qlo,
    const bf16* __restrict__ khi, const bf16* __restrict__ klo,
    const uint32_t* __restrict__ vphi, const uint32_t* __restrict__ vplo,
    const float* __restrict__ corr,
    bf16* __restrict__ ohi, bf16* __restrict__ olo)
{
    extern __shared__ uint8_t sraw[];
    int tid = threadIdx.x;
    int wid = tid >> 5, lane = tid & 31;
    int r = lane >> 2, qc = lane & 3;
    int y = blockIdx.y;
    int h = y & 15;
    int l0 = blockIdx.x * 64;
    int lr = l0 + wid * 16 + r;

    uint32_t sb = (uint32_t)__cvta_generic_to_shared(sraw);

    auto load_stage = [&](int st, uint32_t sbase) {
        int s0 = st * 64;
        size_t kbase = ((size_t)y * L_SEQ + s0) * DQKh;
        #pragma unroll
        for (int i = 0; i < 8; i++) {
            int c = tid + i * 128;
            int row = c >> 4, ch = (c & 15) * 8;
            uint32_t dst = sbase + (uint32_t)(row * 288 + (c & 15) * 16);
            CP16(dst + AT_KHI, khi + kbase + row * 128 + ch);
            CP16(dst + AT_KLO, klo + kbase + row * 128 + ch);
        }
        size_t vbase = ((size_t)y * (L_SEQ / 2) + st * 32) * DVh;
        #pragma unroll
        for (int i = 0; i < 4; i++) {
            int c = tid + i * 128;
            int s2 = c >> 4, ch = (c & 15) * 4;
            uint32_t dst = sbase + (uint32_t)(s2 * 288 + ch * 4);
            CP16(dst + AT_VHI, vphi + vbase + s2 * 64 + ch);
            CP16(dst + AT_VLO, vplo + vbase + s2 * 64 + ch);
        }
    };

    // masked Q fragments in registers (q stored perm-d -> uint2 frag loads)
    uint32_t qa[8][2][4];
    {
        size_t rb0 = ((size_t)y * L_SEQ + lr) * DQKh;
        size_t rb1 = rb0 + 8 * DQKh;
        int ws0 = (h == 0) ? 0 : g_ws[h * L_SEQ + lr];
        int ws1 = (h == 0) ? 0 : g_ws[h * L_SEQ + lr + 8];
        #pragma unroll
        for (int ks = 0; ks < 8; ks++) {
            int po = ks * 16 + 4 * qc;       // permuted offset
            int d0 = ks * 16 + 2 * qc;       // original d of first pair
            int d2 = d0 + 8;                 // original d of second pair
            uint2 H0 = *(const uint2*)(qhi + rb0 + po);  // {a0, a2}
            uint2 H1 = *(const uint2*)(qhi + rb1 + po);  // {a1, a3}
            uint2 L0 = *(const uint2*)(qlo + rb0 + po);
            uint2 L1 = *(const uint2*)(qlo + rb1 + po);
            uint32_t a0 = H0.x, a2 = H0.y, a1 = H1.x, a3 = H1.y;
            uint32_t c0 = L0.x, c2 = L0.y, c1 = L1.x, c3 = L1.y;
            if (h != 0) {
                a0 = mpair(a0, d0, ws0); a1 = mpair(a1, d0, ws1);
                a2 = mpair(a2, d2, ws0); a3 = mpair(a3, d2, ws1);
                c0 = mpair(c0, d0, ws0); c1 = mpair(c1, d0, ws1);
                c2 = mpair(c2, d2, ws0); c3 = mpair(c3, d2, ws1);
            }
            qa[ks][0][0] = a0; qa[ks][0][1] = a1;
            qa[ks][0][2] = a2; qa[ks][0][3] = a3;
            qa[ks][1][0] = c0; qa[ks][1][1] = c1;
            qa[ks][1][2] = c2; qa[ks][1][3] = c3;
        }
    }

    load_stage(0, sb);
    CP_COMMIT();

    float oacc[8][4] = {};
    float den0 = 0.f, den1 = 0.f;

    for (int st = 0; st < 32; st++) {
        CP_WAIT0();
        __syncthreads();
        if (st + 1 < 32) { load_stage(st + 1, sb + ((st + 1) & 1) * AT_STAGE); CP_COMMIT(); }

        uint8_t* stg = sraw + (st & 1) * AT_STAGE;
        bf16* sKhi = (bf16*)(stg + AT_KHI);
        bf16* sKlo = (bf16*)(stg + AT_KLO);
        uint32_t* sVhiP = (uint32_t*)(stg + AT_VHI);
        uint32_t* sVloP = (uint32_t*)(stg + AT_VLO);

        // S = Qmasked @ Kmasked^T (3-term split); K b-frags as single LDS64
        float sacc[8][4] = {};
        #pragma unroll
        for (int ks = 0; ks < 8; ks++) {
            #pragma unroll
            for (int nt = 0; nt < 8; nt++) {
                int so = (nt * 8 + r) * 144 + ks * 16 + 4 * qc;
                uint2 bh = *(const uint2*)&sKhi[so];
                uint2 bl = *(const uint2*)&sKlo[so];
                mma_bf16(sacc[nt], qa[ks][0], bh.x, bh.y);
                mma_bf16(sacc[nt], qa[ks][0], bl.x, bl.y);
                mma_bf16(sacc[nt], qa[ks][1], bh.x, bh.y);
            }
        }

        // global-key correction
        if (st == 0) {
            #pragma unroll
            for (int nt = 0; nt < 2; nt++) {
                size_t c0i = ((size_t)y * L_SEQ + lr) * 32 + nt * 8 + 2 * qc;
                size_t c1i = c0i + 8 * 32;
                sacc[nt][0] += corr[c0i]; sacc[nt][1] += corr[c0i + 1];
                sacc[nt][2] += corr[c1i]; sacc[nt][3] += corr[c1i + 1];
            }
        } else if (st == 31) {
            #pragma unroll
            for (int i2 = 0; i2 < 2; i2++) {
                int nt = 6 + i2;
                size_t c0i = ((size_t)y * L_SEQ + lr) * 32 + 16 + i2 * 8 + 2 * qc;
                size_t c1i = c0i + 8 * 32;
                sacc[nt][0] += corr[c0i]; sacc[nt][1] += corr[c0i + 1];
                sacc[nt][2] += corr[c1i]; sacc[nt][3] += corr[c1i + 1];
            }
        }

        // denominator partials
        #pragma unroll
        for (int nt = 0; nt < 8; nt++) {
            den0 += sacc[nt][0] + sacc[nt][1];
            den1 += sacc[nt][2] + sacc[nt][3];
        }

        // O += S @ V (S frags re-split to bf16 as A fragments)
        #pragma unroll
        for (int kk = 0; kk < 4; kk++) {
            uint32_t ahi[4], alo[4];
            split_pack(sacc[2 * kk][0],     sacc[2 * kk][1],     ahi[0], alo[0]);
            split_pack(sacc[2 * kk][2],     sacc[2 * kk][3],     ahi[1], alo[1]);
            split_pack(sacc[2 * kk + 1][0], sacc[2 * kk + 1][1], ahi[2], alo[2]);
            split_pack(sacc[2 * kk + 1][2], sacc[2 * kk + 1][3], ahi[3], alo[3]);
            #pragma unroll
            for (int nt = 0; nt < 8; nt++) {
                int vo = (kk * 8 + qc) * 72 + nt * 8 + r;
                uint32_t bh0 = sVhiP[vo], bh1 = sVhiP[vo + 4 * 72];
                uint32_t bl0 = sVloP[vo], bl1 = sVloP[vo + 4 * 72];
                mma_bf16(oacc[nt], ahi, bh0, bh1);
                mma_bf16(oacc[nt], ahi, bl0, bl1);
                mma_bf16(oacc[nt], alo, bh0, bh1);
            }
        }
    }

    den0 += __shfl_xor_sync(0xffffffffu, den0, 1);
    den0 += __shfl_xor_sync(0xffffffffu, den0, 2);
    den1 += __shfl_xor_sync(0xffffffffu, den1, 1);
    den1 += __shfl_xor_sync(0xffffffffu, den1, 2);
    float inv0 = 1.0f / fmaxf(den0, 1e-12f);
    float inv1 = 1.0f / fmaxf(den1, 1e-12f);

    // store at planes with perm-d (out_gemm's K-dim) — matched by permuted Wo
    int b = y >> 4;
    int row0 = (lr)     * BATCH + b;
    int row1 = (lr + 8) * BATCH + b;
    #pragma unroll
    for (int nt = 0; nt < 8; nt++) {
        int dp = permd(h * DVh + nt * 8 + 2 * qc);
        store_hl(ohi, olo, (size_t)row0 * EMB + dp,
                 oacc[nt][0] * inv0, oacc[nt][1] * inv0);
        store_hl(ohi, olo, (size_t)row1 * EMB + dp,
                 oacc[nt][2] * inv1, oacc[nt][3] * inv1);
    }
}

// ---------------- launch ------------------------------------------------------
extern "C" void kernel_launch(void* const* d_in, const int* in_sizes, int n_in,
                              void* d_out, int out_size)
{
    (void)in_sizes; (void)n_in; (void)out_size;
    const float* query = (const float*)d_in[0];
    const float* key_  = (const float*)d_in[1];
    const float* value = (const float*)d_in[2];
    const float* Wq    = (const float*)d_in[3];
    const float* bq    = (const float*)d_in[4];
    const float* Wk    = (const float*)d_in[5];
    const float* bk    = (const float*)d_in[6];
    const float* Wv    = (const float*)d_in[7];
    const float* bv    = (const float*)d_in[8];
    const float* Wo    = (const float*)d_in[9];
    const float* bo    = (const float*)d_in[10];
    float* out = (float*)d_out;

    bf16 *inq_hi,*inq_lo,*ink_hi,*ink_lo,*inv_hi,*inv_lo;
    bf16 *wq_hi,*wq_lo,*wk_hi,*wk_lo,*wv_hi,*wv_lo,*wo_hi,*wo_lo;
    bf16 *q_hi,*q_lo,*k_hi,*k_lo,*v_hi,*v_lo,*at_hi,*at_lo;
    uint32_t *vp_hi,*vp_lo;
    float *corr,*kg;
    cudaGetSymbolAddress((void**)&inq_hi, g_inq_hi);
    cudaGetSymbolAddress((void**)&inq_lo, g_inq_lo);
    cudaGetSymbolAddress((void**)&ink_hi, g_ink_hi);
    cudaGetSymbolAddress((void**)&ink_lo, g_ink_lo);
    cudaGetSymbolAddress((void**)&inv_hi, g_inv_hi);
    cudaGetSymbolAddress((void**)&inv_lo, g_inv_lo);
    cudaGetSymbolAddress((void**)&wq_hi, g_wq_hi);
    cudaGetSymbolAddress((void**)&wq_lo, g_wq_lo);
    cudaGetSymbolAddress((void**)&wk_hi, g_wk_hi);
    cudaGetSymbolAddress((void**)&wk_lo, g_wk_lo);
    cudaGetSymbolAddress((void**)&wv_hi, g_wv_hi);
    cudaGetSymbolAddress((void**)&wv_lo, g_wv_lo);
    cudaGetSymbolAddress((void**)&wo_hi, g_wo_hi);
    cudaGetSymbolAddress((void**)&wo_lo, g_wo_lo);
    cudaGetSymbolAddress((void**)&q_hi, g_q_hi);
    cudaGetSymbolAddress((void**)&q_lo, g_q_lo);
    cudaGetSymbolAddress((void**)&k_hi, g_k_hi);
    cudaGetSymbolAddress((void**)&k_lo, g_k_lo);
    cudaGetSymbolAddress((void**)&v_hi, g_v_hi);
    cudaGetSymbolAddress((void**)&v_lo, g_v_lo);
    cudaGetSymbolAddress((void**)&vp_hi, g_vp_hi);
    cudaGetSymbolAddress((void**)&vp_lo, g_vp_lo);
    cudaGetSymbolAddress((void**)&at_hi, g_at_hi);
    cudaGetSymbolAddress((void**)&at_lo, g_at_lo);
    cudaGetSymbolAddress((void**)&corr, g_corr);
    cudaGetSymbolAddress((void**)&kg, g_kg);

    const int GEMM_SMEM = 3 * GSTAGE;   // 49152
    cudaFuncSetAttribute(proj_gemm, cudaFuncAttributeMaxDynamicSharedMemorySize, GEMM_SMEM);
    cudaFuncSetAttribute(out_gemm,  cudaFuncAttributeMaxDynamicSharedMemorySize, GEMM_SMEM);
    const int ATTN_SMEM = 2 * AT_STAGE; // 110592
    cudaFuncSetAttribute(attn_mma, cudaFuncAttributeMaxDynamicSharedMemorySize, ATTN_SMEM);

    build_ws_kernel<<<(NH * L_SEQ + 255) / 256, 256>>>();

    CvtArgs ca;
    ca.src[0] = query; ca.hi[0] = inq_hi; ca.lo[0] = inq_lo;
    ca.src[1] = key_;  ca.hi[1] = ink_hi; ca.lo[1] = ink_lo;
    ca.src[2] = value; ca.hi[2] = inv_hi; ca.lo[2] = inv_lo;
    ca.src[3] = Wq;    ca.hi[3] = wq_hi;  ca.lo[3] = wq_lo;
    ca.src[4] = Wk;    ca.hi[4] = wk_hi;  ca.lo[4] = wk_lo;
    ca.src[5] = Wv;    ca.hi[5] = wv_hi;  ca.lo[5] = wv_lo;
    ca.src[6] = Wo;    ca.hi[6] = wo_hi;  ca.lo[6] = wo_lo;
    cvt_all<<<18432, 256>>>(ca);

    ProjArgs pa;
    pa.aq_hi = inq_hi; pa.aq_lo = inq_lo;
    pa.ak_hi = ink_hi; pa.ak_lo = ink_lo;
    pa.av_hi = inv_hi; pa.av_lo = inv_lo;
    pa.wq_hi = wq_hi; pa.wq_lo = wq_lo;
    pa.wk_hi = wk_hi; pa.wk_lo = wk_lo;
    pa.wv_hi = wv_hi; pa.wv_lo = wv_lo;
    pa.bq = bq; pa.bk = bk; pa.bv = bv;
    pa.q_hi = q_hi; pa.q_lo = q_lo;
    pa.k_hi = k_hi; pa.k_lo = k_lo;
    pa.v_hi = v_hi; pa.v_lo = v_lo;
    pa.kg = kg;
    pa.scale = 1.0f / sqrtf((float)QKD);
    proj_gemm<<<dim3(QKD / 128, NROWS / 128, 3), 128, GEMM_SMEM>>>(pa);

    const int NVP8 = BATCH * NH * (L_SEQ / 2) * DVh / 8;
    vpack_kernel<<<NVP8 / 256, 256>>>(v_hi, v_lo, vp_hi, vp_lo);

    corr_kernel<<<dim3(L_SEQ / 128, BATCH * NH), 256>>>(q_hi, q_lo, kg, corr);

    attn_mma<<<dim3(L_SEQ / 64, BATCH * NH), 128, ATTN_SMEM>>>(
        q_hi, q_lo, k_hi, k_lo, vp_hi, vp_lo, corr, at_hi, at_lo);

    out_gemm<<<dim3(EMB / 128, NROWS / 128), 128, GEMM_SMEM>>>(
        at_hi, at_lo, wo_hi, wo_lo, bo, out);
}

// round 15
// speedup vs baseline: 1.0657x; 1.0657x over previous
#include <cuda_runtime.h>
#include <cuda_bf16.h>
#include <stdint.h>
#include <math.h>

#define L_SEQ 2048
#define BATCH 2
#define EMB   1024
#define NH    16
#define DQKh  128
#define QKD   2048
#define DVh   64
#define NROWS 4096

typedef __nv_bfloat16 bf16;

// ---------------- scratch (static device globals; no allocation) -------------
__device__ bf16 g_inq_hi[(size_t)NROWS*EMB];
__device__ bf16 g_inq_lo[(size_t)NROWS*EMB];
__device__ bf16 g_ink_hi[(size_t)NROWS*EMB];
__device__ bf16 g_ink_lo[(size_t)NROWS*EMB];
__device__ bf16 g_inv_hi[(size_t)NROWS*EMB];
__device__ bf16 g_inv_lo[(size_t)NROWS*EMB];
__device__ bf16 g_wq_hi[(size_t)QKD*EMB];
__device__ bf16 g_wq_lo[(size_t)QKD*EMB];
__device__ bf16 g_wk_hi[(size_t)QKD*EMB];
__device__ bf16 g_wk_lo[(size_t)QKD*EMB];
__device__ bf16 g_wv_hi[(size_t)EMB*EMB];
__device__ bf16 g_wv_lo[(size_t)EMB*EMB];
__device__ bf16 g_wo_hi[(size_t)EMB*EMB];
__device__ bf16 g_wo_lo[(size_t)EMB*EMB];
__device__ bf16 g_q_hi[(size_t)BATCH*NH*L_SEQ*DQKh];
__device__ bf16 g_q_lo[(size_t)BATCH*NH*L_SEQ*DQKh];
__device__ bf16 g_k_hi[(size_t)BATCH*NH*L_SEQ*DQKh];   // pre-masked
__device__ bf16 g_k_lo[(size_t)BATCH*NH*L_SEQ*DQKh];   // pre-masked
__device__ uint32_t g_vp_hi[(size_t)BATCH*NH*(L_SEQ/2)*DVh]; // paired (s,s+1)
__device__ uint32_t g_vp_lo[(size_t)BATCH*NH*(L_SEQ/2)*DVh];
__device__ float g_kg[(size_t)BATCH*NH*32*DQKh];       // unmasked global k rows
__device__ bf16 g_at_hi[(size_t)NROWS*EMB];
__device__ bf16 g_at_lo[(size_t)NROWS*EMB];
__device__ float g_corr[(size_t)BATCH*NH*L_SEQ*32];
__device__ int   g_ws[NH*L_SEQ];

// ---------------- asm helpers -------------------------------------------------
__device__ __forceinline__ void mma_bf16(float c[4], const uint32_t a[4],
                                         uint32_t b0, uint32_t b1) {
    asm volatile(
        "mma.sync.aligned.m16n8k16.row.col.f32.bf16.bf16.f32 "
        "{%0,%1,%2,%3},{%4,%5,%6,%7},{%8,%9},{%0,%1,%2,%3};"
        : "+f"(c[0]), "+f"(c[1]), "+f"(c[2]), "+f"(c[3])
        : "r"(a[0]), "r"(a[1]), "r"(a[2]), "r"(a[3]), "r"(b0), "r"(b1));
}

#define CP16(dst, src) \
    asm volatile("cp.async.cg.shared.global [%0], [%1], 16;" \
                 :: "r"(dst), "l"(src))
#define CP_COMMIT() asm volatile("cp.async.commit_group;")
#define CP_WAIT1()  asm volatile("cp.async.wait_group 1;")
#define CP_WAIT0()  asm volatile("cp.async.wait_group 0;")

__device__ __forceinline__ uint32_t mpair(uint32_t v, int d, int ws) {
    uint32_t m = 0;
    if ((unsigned)(d - ws) < 32u)     m |= 0x0000FFFFu;
    if ((unsigned)(d + 1 - ws) < 32u) m |= 0xFFFF0000u;
    return v & m;
}

__device__ __forceinline__ void split_pack(float x, float y,
                                           uint32_t& hi, uint32_t& lo) {
    __nv_bfloat16 hx = __float2bfloat16(x), hy = __float2bfloat16(y);
    __nv_bfloat162 ph; ph.x = hx; ph.y = hy;
    hi = *(uint32_t*)&ph;
    __nv_bfloat162 pl;
    pl.x = __float2bfloat16(x - __bfloat162float(hx));
    pl.y = __float2bfloat16(y - __bfloat162float(hy));
    lo = *(uint32_t*)&pl;
}

__device__ __forceinline__ void store_hl(bf16* hip, bf16* lop, size_t idx,
                                         float v0, float v1) {
    __nv_bfloat16 h0 = __float2bfloat16(v0), h1 = __float2bfloat16(v1);
    __nv_bfloat162 hh; hh.x = h0; hh.y = h1;
    *(__nv_bfloat162*)(hip + idx) = hh;
    __nv_bfloat162 ll;
    ll.x = __float2bfloat16(v0 - __bfloat162float(h0));
    ll.y = __float2bfloat16(v1 - __bfloat162float(h1));
    *(__nv_bfloat162*)(lop + idx) = ll;
}

// ---------------- setup kernels ----------------------------------------------
__global__ void build_ws_kernel() {
    int idx = blockIdx.x * blockDim.x + threadIdx.x;
    if (idx >= NH * L_SEQ) return;
    int h = idx / L_SEQ, l = idx % L_SEQ;
    int ws = 0;
    if (h > 0) {
        int rn = 96 / h + 1;
        int i = l / rn, m = l % rn;
        int mm = (i & 1) ? (rn - 1 - m) : m;
        ws = mm * h;
    }
    g_ws[idx] = ws;
}

// one fused vectorized conversion of all 7 tensors (float4 per thread)
struct CvtArgs { const float* src[7]; bf16* hi[7]; bf16* lo[7]; };

__global__ void __launch_bounds__(256) cvt_all(CvtArgs a) {
    int t = blockIdx.x * 256 + threadIdx.x;   // float4 unit index
    int seg, j;
    if      (t < 1048576) { seg = 0; j = t; }
    else if (t < 2097152) { seg = 1; j = t - 1048576; }
    else if (t < 3145728) { seg = 2; j = t - 2097152; }
    else if (t < 3670016) { seg = 3; j = t - 3145728; }
    else if (t < 4194304) { seg = 4; j = t - 3670016; }
    else if (t < 4456448) { seg = 5; j = t - 4194304; }
    else                  { seg = 6; j = t - 4456448; }
    float4 x = ((const float4*)a.src[seg])[j];
    uint32_t h0, l0, h1, l1;
    split_pack(x.x, x.y, h0, l0);
    split_pack(x.z, x.w, h1, l1);
    ((uint2*)a.hi[seg])[j] = make_uint2(h0, h1);
    ((uint2*)a.lo[seg])[j] = make_uint2(l0, l1);
}

// ---------------- GEMM core: 128x128, 4 warps 64x64, cp.async x3, 1 barrier --
// MODE 0: fp32 out [M,N]
// MODE 1: relu*scale -> bf16 hi/lo planes [(b h) l d], D=128  (q, unmasked)
// MODE 2: linear -> DIRECT paired vp u32 planes (fused vpack)
// MODE 3: relu -> MASKED bf16 planes D=128 (k) + unmasked fp32 g_kg side rows
#define GSTAGE 24576

template <int MODE>
__device__ __forceinline__ void gemm_body(
    const bf16* __restrict__ Ahi, const bf16* __restrict__ Alo,
    const bf16* __restrict__ Whi, const bf16* __restrict__ Wlo,
    const float* __restrict__ bias,
    float* __restrict__ Cf, bf16* __restrict__ Ohi, bf16* __restrict__ Olo,
    float* __restrict__ kg,
    uint32_t* __restrict__ VPhi, uint32_t* __restrict__ VPlo,
    int N, int K, float scale)
{
    extern __shared__ bf16 gsm[];
    int tid = threadIdx.x;
    int wid = tid >> 5, lane = tid & 31;
    int r = lane >> 2, qc = lane & 3;
    int warp_m = (wid >> 1) * 64, warp_n = (wid & 1) * 64;
    int m0 = blockIdx.y * 128, n0 = blockIdx.x * 128;

    const bf16* pAh = Ahi + (size_t)m0 * K;
    const bf16* pAl = Alo + (size_t)m0 * K;
    const bf16* pWh = Whi + (size_t)n0 * K;
    const bf16* pWl = Wlo + (size_t)n0 * K;

    uint32_t sb = (uint32_t)__cvta_generic_to_shared(gsm);

    auto load_stage = [&](int kt, uint32_t sbase) {
        #pragma unroll
        for (int i = 0; i < 2; i++) {
            int c = tid + i * 128;
            int row = c >> 1, half = (c & 1) * 8;
            uint32_t dst = sbase + (uint32_t)(row * 24 + half) * 2;
            size_t off = (size_t)row * K + kt + half;
            CP16(dst,         pAh + off);
            CP16(dst +  6144, pAl + off);
            CP16(dst + 12288, pWh + off);
            CP16(dst + 18432, pWl + off);
        }
    };

    // 3-stage ring: prologue fills stages 0 and 1
    load_stage(0, sb);
    CP_COMMIT();
    load_stage(16, sb + GSTAGE);
    CP_COMMIT();

    float acc[4][8][4] = {};
    int T = K >> 4;
    int cur = 0, pf = 2;   // compute stage / prefetch stage indices (mod 3)
    for (int t = 0; t < T; t++) {
        if (t < T - 1) { CP_WAIT1(); } else { CP_WAIT0(); }
        __syncthreads();   // single barrier: stage t visible AND compute t-1 done
        if (t + 2 < T) { load_stage((t + 2) << 4, sb + pf * GSTAGE); CP_COMMIT(); }

        bf16* sAh = gsm + cur * (GSTAGE / 2);
        bf16* sAl = sAh + 3072;
        bf16* sWh = sAl + 3072;
        bf16* sWl = sWh + 3072;

        uint32_t af[2][4][4];
        #pragma unroll
        for (int mt = 0; mt < 4; mt++) {
            int row = warp_m + mt * 16 + r;
            af[0][mt][0] = *(const uint32_t*)&sAh[row * 24 + 2 * qc];
            af[0][mt][1] = *(const uint32_t*)&sAh[(row + 8) * 24 + 2 * qc];
            af[0][mt][2] = *(const uint32_t*)&sAh[row * 24 + 2 * qc + 8];
            af[0][mt][3] = *(const uint32_t*)&sAh[(row + 8) * 24 + 2 * qc + 8];
            af[1][mt][0] = *(const uint32_t*)&sAl[row * 24 + 2 * qc];
            af[1][mt][1] = *(const uint32_t*)&sAl[(row + 8) * 24 + 2 * qc];
            af[1][mt][2] = *(const uint32_t*)&sAl[row * 24 + 2 * qc + 8];
            af[1][mt][3] = *(const uint32_t*)&sAl[(row + 8) * 24 + 2 * qc + 8];
        }
        #pragma unroll
        for (int nt = 0; nt < 8; nt++) {
            int wrow = warp_n + nt * 8 + r;
            uint32_t bh0 = *(const uint32_t*)&sWh[wrow * 24 + 2 * qc];
            uint32_t bh1 = *(const uint32_t*)&sWh[wrow * 24 + 2 * qc + 8];
            uint32_t bl0 = *(const uint32_t*)&sWl[wrow * 24 + 2 * qc];
            uint32_t bl1 = *(const uint32_t*)&sWl[wrow * 24 + 2 * qc + 8];
            #pragma unroll
            for (int mt = 0; mt < 4; mt++) {
                mma_bf16(acc[mt][nt], af[0][mt], bh0, bh1);
                mma_bf16(acc[mt][nt], af[0][mt], bl0, bl1);
                mma_bf16(acc[mt][nt], af[1][mt], bh0, bh1);
            }
        }
        cur = (cur == 2) ? 0 : cur + 1;
        pf  = (pf == 2)  ? 0 : pf + 1;
    }

    if (MODE == 2) {
        // fused vpack: stage C-tile in smem, emit paired vp u32 planes directly.
        __syncthreads();   // all warps done reading the cp.async ring
        uint32_t* sHi = (uint32_t*)gsm;        // [128 rows][64 col-pairs] 32KB
        uint32_t* sLo = sHi + 128 * 64;        // 32KB (total 64KB <= 72KB ring)
        #pragma unroll
        for (int mt = 0; mt < 4; mt++) {
            #pragma unroll
            for (int nt = 0; nt < 8; nt++) {
                int rl0 = warp_m + mt * 16 + r;
                int rl1 = rl0 + 8;
                int cl  = warp_n + nt * 8 + 2 * qc;
                float b0f = bias[n0 + cl], b1f = bias[n0 + cl + 1];
                uint32_t h0, l0u, h1, l1u;
                split_pack(acc[mt][nt][0] + b0f, acc[mt][nt][1] + b1f, h0, l0u);
                split_pack(acc[mt][nt][2] + b0f, acc[mt][nt][3] + b1f, h1, l1u);
                int c2 = cl >> 1;
                sHi[rl0 * 64 + c2] = h0;  sHi[rl1 * 64 + c2] = h1;
                sLo[rl0 * 64 + c2] = l0u; sLo[rl1 * 64 + c2] = l1u;
            }
        }
        __syncthreads();
        // rows = l*BATCH+b; block rows m0..m0+127 -> l in [m0/2, m0/2+64), both b.
        // vp[y][s2][d] pairs (l=2*s2, 2*s2+1) at same b. local row for (l,b):
        //   l = m0/2 + 2*j + e  ->  rowloc = 4*j + 2*e + b
        int s2base = m0 >> 2;
        int hbase  = n0 >> 6;    // two heads per block
        #pragma unroll
        for (int it = 0; it < 32; it++) {
            int u = tid + it * 128;          // 4096 units: c2loc(64) x j(32) x b(2)
            int c2loc = u & 63;
            int j = (u >> 6) & 31;
            int b = u >> 11;
            int rA = 4 * j + b, rB = rA + 2;
            uint32_t hA = sHi[rA * 64 + c2loc], hB = sHi[rB * 64 + c2loc];
            uint32_t lA = sLo[rA * 64 + c2loc], lB = sLo[rB * 64 + c2loc];
            int hh = c2loc >> 5, d2 = c2loc & 31;
            int y = b * NH + hbase + hh;
            size_t o = ((size_t)y * (L_SEQ / 2) + s2base + j) * DVh + 2 * d2;
            *(uint2*)(VPhi + o) = make_uint2(__byte_perm(hA, hB, 0x5410),
                                             __byte_perm(hA, hB, 0x7632));
            *(uint2*)(VPlo + o) = make_uint2(__byte_perm(lA, lB, 0x5410),
                                             __byte_perm(lA, lB, 0x7632));
        }
        return;
    }

    #pragma unroll
    for (int mt = 0; mt < 4; mt++) {
        #pragma unroll
        for (int nt = 0; nt < 8; nt++) {
            int row0 = m0 + warp_m + mt * 16 + r;
            int row1 = row0 + 8;
            int col  = n0 + warp_n + nt * 8 + 2 * qc;
            float b0f = bias[col], b1f = bias[col + 1];
            float v00 = acc[mt][nt][0] + b0f, v01 = acc[mt][nt][1] + b1f;
            float v10 = acc[mt][nt][2] + b0f, v11 = acc[mt][nt][3] + b1f;
            if (MODE == 1 || MODE == 3) {
                v00 = fmaxf(v00, 0.f) * scale; v01 = fmaxf(v01, 0.f) * scale;
                v10 = fmaxf(v10, 0.f) * scale; v11 = fmaxf(v11, 0.f) * scale;
            }
            if (MODE == 0) {
                *(float2*)(Cf + (size_t)row0 * N + col) = make_float2(v00, v01);
                *(float2*)(Cf + (size_t)row1 * N + col) = make_float2(v10, v11);
            } else if (MODE == 1) {
                int h = col >> 7, d = col & 127;
                store_hl(Ohi, Olo,
                    ((size_t)((row0 & 1) * NH + h) * L_SEQ + (row0 >> 1)) * DQKh + d,
                    v00, v01);
                store_hl(Ohi, Olo,
                    ((size_t)((row1 & 1) * NH + h) * L_SEQ + (row1 >> 1)) * DQKh + d,
                    v10, v11);
            } else if (MODE == 3) {
                int h = col >> 7, d = col & 127;
                int l0i = row0 >> 1, b0i = row0 & 1;
                int l1i = row1 >> 1, b1i = row1 & 1;
                if (l0i < 16 || l0i >= L_SEQ - 16) {
                    int j = (l0i < 16) ? l0i : (l0i - (L_SEQ - 32));
                    size_t o = ((size_t)(b0i * NH + h) * 32 + j) * DQKh + d;
                    kg[o] = v00; kg[o + 1] = v01;
                }
                if (l1i < 16 || l1i >= L_SEQ - 16) {
                    int j = (l1i < 16) ? l1i : (l1i - (L_SEQ - 32));
                    size_t o = ((size_t)(b1i * NH + h) * 32 + j) * DQKh + d;
                    kg[o] = v10; kg[o + 1] = v11;
                }
                if (h != 0) {
                    int ws0 = g_ws[h * L_SEQ + l0i];
                    int ws1 = g_ws[h * L_SEQ + l1i];
                    if ((unsigned)(d - ws0) >= 32u)     v00 = 0.f;
                    if ((unsigned)(d + 1 - ws0) >= 32u) v01 = 0.f;
                    if ((unsigned)(d - ws1) >= 32u)     v10 = 0.f;
                    if ((unsigned)(d + 1 - ws1) >= 32u) v11 = 0.f;
                }
                store_hl(Ohi, Olo,
                    ((size_t)(b0i * NH + h) * L_SEQ + l0i) * DQKh + d, v00, v01);
                store_hl(Ohi, Olo,
                    ((size_t)(b1i * NH + h) * L_SEQ + l1i) * DQKh + d, v10, v11);
            }
        }
    }
}

// fused q/k/v projection: z=0 -> q (MODE1), z=1 -> k (MODE3), z=2 -> v (MODE2)
struct ProjArgs {
    const bf16 *aq_hi, *aq_lo, *ak_hi, *ak_lo, *av_hi, *av_lo;
    const bf16 *wq_hi, *wq_lo, *wk_hi, *wk_lo, *wv_hi, *wv_lo;
    const float *bq, *bk, *bv;
    bf16 *q_hi, *q_lo, *k_hi, *k_lo;
    uint32_t *vp_hi, *vp_lo;
    float* kg;
    float scale;
};

__global__ void __launch_bounds__(128) proj_gemm(ProjArgs p) {
    int z = blockIdx.z;
    if (z == 0) {
        gemm_body<1>(p.aq_hi, p.aq_lo, p.wq_hi, p.wq_lo, p.bq,
                     nullptr, p.q_hi, p.q_lo, nullptr, nullptr, nullptr,
                     QKD, EMB, p.scale);
    } else if (z == 1) {
        gemm_body<3>(p.ak_hi, p.ak_lo, p.wk_hi, p.wk_lo, p.bk,
                     nullptr, p.k_hi, p.k_lo, p.kg, nullptr, nullptr,
                     QKD, EMB, 1.0f);
    } else {
        if (blockIdx.x >= EMB / 128) return;
        gemm_body<2>(p.av_hi, p.av_lo, p.wv_hi, p.wv_lo, p.bv,
                     nullptr, nullptr, nullptr, nullptr, p.vp_hi, p.vp_lo,
                     EMB, EMB, 1.0f);
    }
}

__global__ void __launch_bounds__(128) out_gemm(
    const bf16* __restrict__ Ahi, const bf16* __restrict__ Alo,
    const bf16* __restrict__ Whi, const bf16* __restrict__ Wlo,
    const float* __restrict__ bias, float* __restrict__ Cf)
{
    gemm_body<0>(Ahi, Alo, Whi, Wlo, bias, Cf, nullptr, nullptr, nullptr,
                 nullptr, nullptr, EMB, EMB, 1.0f);
}

// ---------------- global-key correction: corr[y,l,j] = q[l]·kg[j] ------------
__global__ void __launch_bounds__(256) corr_kernel(
    const bf16* __restrict__ qhi, const bf16* __restrict__ qlo,
    const float* __restrict__ kg, float* __restrict__ corr)
{
    __shared__ float sKg[32][128];
    int tid = threadIdx.x;
    int y = blockIdx.y;
    int l0 = blockIdx.x * 128;

    for (int i = tid; i < 32 * 128; i += 256)
        sKg[i >> 7][i & 127] = kg[(size_t)y * 32 * 128 + i];
    __syncthreads();

    int l = l0 + (tid >> 1);
    int jb = (tid & 1) * 16;
    float acc[16] = {};
    size_t qb = ((size_t)y * L_SEQ + l) * DQKh;
    for (int d = 0; d < 128; d += 2) {
        uint32_t ph = *(const uint32_t*)(qhi + qb + d);
        uint32_t pl = *(const uint32_t*)(qlo + qb + d);
        __nv_bfloat162 h2 = *(__nv_bfloat162*)&ph;
        __nv_bfloat162 l2 = *(__nv_bfloat162*)&pl;
        float q0 = __bfloat162float(h2.x) + __bfloat162float(l2.x);
        float q1 = __bfloat162float(h2.y) + __bfloat162float(l2.y);
        #pragma unroll
        for (int j = 0; j < 16; j++)
            acc[j] += q0 * sKg[jb + j][d] + q1 * sKg[jb + j][d + 1];
    }
    float* cp = corr + ((size_t)y * L_SEQ + l) * 32 + jb;
    #pragma unroll
    for (int j = 0; j < 16; j++) cp[j] = acc[j];
}

// ---------------- attention: 128 thr, 64 q-rows, cp.async x2, 1 barrier ------
#define AT_KHI 0
#define AT_KLO 17408
#define AT_VHI 34816
#define AT_VLO 44032
#define AT_STAGE 53248

__global__ void __launch_bounds__(128) attn_mma(
    const bf16* __restrict__ qhi, const bf16* __restrict__ qlo,
    const bf16* __restrict__ khi, const bf16* __restrict__ klo,
    const uint32_t* __restrict__ vphi, const uint32_t* __restrict__ vplo,
    const float* __restrict__ corr,
    bf16* __restrict__ ohi, bf16* __restrict__ olo)
{
    extern __shared__ uint8_t sraw[];
    int tid = threadIdx.x;
    int wid = tid >> 5, lane = tid & 31;
    int r = lane >> 2, qc = lane & 3;
    int y = blockIdx.y;
    int h = y & 15;
    int l0 = blockIdx.x * 64;
    int lr = l0 + wid * 16 + r;

    uint32_t sb = (uint32_t)__cvta_generic_to_shared(sraw);

    auto load_stage = [&](int st, uint32_t sbase) {
        int s0 = st * 64;
        size_t kbase = ((size_t)y * L_SEQ + s0) * DQKh;
        #pragma unroll
        for (int i = 0; i < 8; i++) {
            int c = tid + i * 128;
            int row = c >> 4, ch = (c & 15) * 8;
            uint32_t dst = sbase + (uint32_t)(row * 272 + ch * 2);
            CP16(dst + AT_KHI, khi + kbase + row * 128 + ch);
            CP16(dst + AT_KLO, klo + kbase + row * 128 + ch);
        }
        size_t vbase = ((size_t)y * (L_SEQ / 2) + st * 32) * DVh;
        #pragma unroll
        for (int i = 0; i < 4; i++) {
            int c = tid + i * 128;
            int s2 = c >> 4, ch = (c & 15) * 4;
            uint32_t dst = sbase + (uint32_t)(s2 * 288 + ch * 4);
            CP16(dst + AT_VHI, vphi + vbase + s2 * 64 + ch);
            CP16(dst + AT_VLO, vplo + vbase + s2 * 64 + ch);
        }
    };

    // masked Q fragments in registers
    uint32_t qa[8][2][4];
    {
        size_t rb0 = ((size_t)y * L_SEQ + lr) * DQKh;
        size_t rb1 = rb0 + 8 * DQKh;
        int ws0 = (h == 0) ? 0 : g_ws[h * L_SEQ + lr];
        int ws1 = (h == 0) ? 0 : g_ws[h * L_SEQ + lr + 8];
        #pragma unroll
        for (int ks = 0; ks < 8; ks++) {
            int d0 = ks * 16 + 2 * qc;
            int d2 = d0 + 8;
            uint32_t a0 = *(const uint32_t*)(qhi + rb0 + d0);
            uint32_t a1 = *(const uint32_t*)(qhi + rb1 + d0);
            uint32_t a2 = *(const uint32_t*)(qhi + rb0 + d2);
            uint32_t a3 = *(const uint32_t*)(qhi + rb1 + d2);
            uint32_t c0 = *(const uint32_t*)(qlo + rb0 + d0);
            uint32_t c1 = *(const uint32_t*)(qlo + rb1 + d0);
            uint32_t c2 = *(const uint32_t*)(qlo + rb0 + d2);
            uint32_t c3 = *(const uint32_t*)(qlo + rb1 + d2);
            if (h != 0) {
                a0 = mpair(a0, d0, ws0); a1 = mpair(a1, d0, ws1);
                a2 = mpair(a2, d2, ws0); a3 = mpair(a3, d2, ws1);
                c0 = mpair(c0, d0, ws0); c1 = mpair(c1, d0, ws1);
                c2 = mpair(c2, d2, ws0); c3 = mpair(c3, d2, ws1);
            }
            qa[ks][0][0] = a0; qa[ks][0][1] = a1;
            qa[ks][0][2] = a2; qa[ks][0][3] = a3;
            qa[ks][1][0] = c0; qa[ks][1][1] = c1;
            qa[ks][1][2] = c2; qa[ks][1][3] = c3;
        }
    }

    load_stage(0, sb);
    CP_COMMIT();

    float oacc[8][4] = {};
    float den0 = 0.f, den1 = 0.f;

    for (int st = 0; st < 32; st++) {
        CP_WAIT0();
        __syncthreads();
        if (st + 1 < 32) { load_stage(st + 1, sb + ((st + 1) & 1) * AT_STAGE); CP_COMMIT(); }

        uint8_t* stg = sraw + (st & 1) * AT_STAGE;
        bf16* sKhi = (bf16*)(stg + AT_KHI);
        bf16* sKlo = (bf16*)(stg + AT_KLO);
        uint32_t* sVhiP = (uint32_t*)(stg + AT_VHI);
        uint32_t* sVloP = (uint32_t*)(stg + AT_VLO);

        // S = Qmasked @ Kmasked^T (3-term split)
        float sacc[8][4] = {};
        #pragma unroll
        for (int ks = 0; ks < 8; ks++) {
            #pragma unroll
            for (int nt = 0; nt < 8; nt++) {
                int so = (nt * 8 + r) * 136 + ks * 16 + 2 * qc;
                uint32_t bh0 = *(const uint32_t*)&sKhi[so];
                uint32_t bh1 = *(const uint32_t*)&sKhi[so + 8];
                uint32_t bl0 = *(const uint32_t*)&sKlo[so];
                uint32_t bl1 = *(const uint32_t*)&sKlo[so + 8];
                mma_bf16(sacc[nt], qa[ks][0], bh0, bh1);
                mma_bf16(sacc[nt], qa[ks][0], bl0, bl1);
                mma_bf16(sacc[nt], qa[ks][1], bh0, bh1);
            }
        }

        // global-key correction
        if (st == 0) {
            #pragma unroll
            for (int nt = 0; nt < 2; nt++) {
                size_t c0i = ((size_t)y * L_SEQ + lr) * 32 + nt * 8 + 2 * qc;
                size_t c1i = c0i + 8 * 32;
                sacc[nt][0] += corr[c0i]; sacc[nt][1] += corr[c0i + 1];
                sacc[nt][2] += corr[c1i]; sacc[nt][3] += corr[c1i + 1];
            }
        } else if (st == 31) {
            #pragma unroll
            for (int i2 = 0; i2 < 2; i2++) {
                int nt = 6 + i2;
                size_t c0i = ((size_t)y * L_SEQ + lr) * 32 + 16 + i2 * 8 + 2 * qc;
                size_t c1i = c0i + 8 * 32;
                sacc[nt][0] += corr[c0i]; sacc[nt][1] += corr[c0i + 1];
                sacc[nt][2] += corr[c1i]; sacc[nt][3] += corr[c1i + 1];
            }
        }

        // denominator partials
        #pragma unroll
        for (int nt = 0; nt < 8; nt++) {
            den0 += sacc[nt][0] + sacc[nt][1];
            den1 += sacc[nt][2] + sacc[nt][3];
        }

        // O += S @ V (S frags re-split to bf16 as A fragments)
        #pragma unroll
        for (int kk = 0; kk < 4; kk++) {
            uint32_t ahi[4], alo[4];
            split_pack(sacc[2 * kk][0],     sacc[2 * kk][1],     ahi[0], alo[0]);
            split_pack(sacc[2 * kk][2],     sacc[2 * kk][3],     ahi[1], alo[1]);
            split_pack(sacc[2 * kk + 1][0], sacc[2 * kk + 1][1], ahi[2], alo[2]);
            split_pack(sacc[2 * kk + 1][2], sacc[2 * kk + 1][3], ahi[3], alo[3]);
            #pragma unroll
            for (int nt = 0; nt < 8; nt++) {
                int vo = (kk * 8 + qc) * 72 + nt * 8 + r;
                uint32_t bh0 = sVhiP[vo], bh1 = sVhiP[vo + 4 * 72];
                uint32_t bl0 = sVloP[vo], bl1 = sVloP[vo + 4 * 72];
                mma_bf16(oacc[nt], ahi, bh0, bh1);
                mma_bf16(oacc[nt], ahi, bl0, bl1);
                mma_bf16(oacc[nt], alo, bh0, bh1);
            }
        }
    }

    den0 += __shfl_xor_sync(0xffffffffu, den0, 1);
    den0 += __shfl_xor_sync(0xffffffffu, den0, 2);
    den1 += __shfl_xor_sync(0xffffffffu, den1, 1);
    den1 += __shfl_xor_sync(0xffffffffu, den1, 2);
    float inv0 = 1.0f / fmaxf(den0, 1e-12f);
    float inv1 = 1.0f / fmaxf(den1, 1e-12f);

    int b = y >> 4;
    int row0 = (lr)     * BATCH + b;
    int row1 = (lr + 8) * BATCH + b;
    #pragma unroll
    for (int nt = 0; nt < 8; nt++) {
        int d = h * DVh + nt * 8 + 2 * qc;
        store_hl(ohi, olo, (size_t)row0 * EMB + d,
                 oacc[nt][0] * inv0, oacc[nt][1] * inv0);
        store_hl(ohi, olo, (size_t)row1 * EMB + d,
                 oacc[nt][2] * inv1, oacc[nt][3] * inv1);
    }
}

// ---------------- launch ------------------------------------------------------
extern "C" void kernel_launch(void* const* d_in, const int* in_sizes, int n_in,
                              void* d_out, int out_size)
{
    (void)in_sizes; (void)n_in; (void)out_size;
    const float* query = (const float*)d_in[0];
    const float* key_  = (const float*)d_in[1];
    const float* value = (const float*)d_in[2];
    const float* Wq    = (const float*)d_in[3];
    const float* bq    = (const float*)d_in[4];
    const float* Wk    = (const float*)d_in[5];
    const float* bk    = (const float*)d_in[6];
    const float* Wv    = (const float*)d_in[7];
    const float* bv    = (const float*)d_in[8];
    const float* Wo    = (const float*)d_in[9];
    const float* bo    = (const float*)d_in[10];
    float* out = (float*)d_out;

    bf16 *inq_hi,*inq_lo,*ink_hi,*ink_lo,*inv_hi,*inv_lo;
    bf16 *wq_hi,*wq_lo,*wk_hi,*wk_lo,*wv_hi,*wv_lo,*wo_hi,*wo_lo;
    bf16 *q_hi,*q_lo,*k_hi,*k_lo,*at_hi,*at_lo;
    uint32_t *vp_hi,*vp_lo;
    float *corr,*kg;
    cudaGetSymbolAddress((void**)&inq_hi, g_inq_hi);
    cudaGetSymbolAddress((void**)&inq_lo, g_inq_lo);
    cudaGetSymbolAddress((void**)&ink_hi, g_ink_hi);
    cudaGetSymbolAddress((void**)&ink_lo, g_ink_lo);
    cudaGetSymbolAddress((void**)&inv_hi, g_inv_hi);
    cudaGetSymbolAddress((void**)&inv_lo, g_inv_lo);
    cudaGetSymbolAddress((void**)&wq_hi, g_wq_hi);
    cudaGetSymbolAddress((void**)&wq_lo, g_wq_lo);
    cudaGetSymbolAddress((void**)&wk_hi, g_wk_hi);
    cudaGetSymbolAddress((void**)&wk_lo, g_wk_lo);
    cudaGetSymbolAddress((void**)&wv_hi, g_wv_hi);
    cudaGetSymbolAddress((void**)&wv_lo, g_wv_lo);
    cudaGetSymbolAddress((void**)&wo_hi, g_wo_hi);
    cudaGetSymbolAddress((void**)&wo_lo, g_wo_lo);
    cudaGetSymbolAddress((void**)&q_hi, g_q_hi);
    cudaGetSymbolAddress((void**)&q_lo, g_q_lo);
    cudaGetSymbolAddress((void**)&k_hi, g_k_hi);
    cudaGetSymbolAddress((void**)&k_lo, g_k_lo);
    cudaGetSymbolAddress((void**)&vp_hi, g_vp_hi);
    cudaGetSymbolAddress((void**)&vp_lo, g_vp_lo);
    cudaGetSymbolAddress((void**)&at_hi, g_at_hi);
    cudaGetSymbolAddress((void**)&at_lo, g_at_lo);
    cudaGetSymbolAddress((void**)&corr, g_corr);
    cudaGetSymbolAddress((void**)&kg, g_kg);

    const int GEMM_SMEM = 3 * GSTAGE;   // 73728
    cudaFuncSetAttribute(proj_gemm, cudaFuncAttributeMaxDynamicSharedMemorySize, GEMM_SMEM);
    cudaFuncSetAttribute(out_gemm,  cudaFuncAttributeMaxDynamicSharedMemorySize, GEMM_SMEM);
    const int ATTN_SMEM = 2 * AT_STAGE;
    cudaFuncSetAttribute(attn_mma, cudaFuncAttributeMaxDynamicSharedMemorySize, ATTN_SMEM);

    build_ws_kernel<<<(NH * L_SEQ + 255) / 256, 256>>>();

    CvtArgs ca;
    ca.src[0] = query; ca.hi[0] = inq_hi; ca.lo[0] = inq_lo;
    ca.src[1] = key_;  ca.hi[1] = ink_hi; ca.lo[1] = ink_lo;
    ca.src[2] = value; ca.hi[2] = inv_hi; ca.lo[2] = inv_lo;
    ca.src[3] = Wq;    ca.hi[3] = wq_hi;  ca.lo[3] = wq_lo;
    ca.src[4] = Wk;    ca.hi[4] = wk_hi;  ca.lo[4] = wk_lo;
    ca.src[5] = Wv;    ca.hi[5] = wv_hi;  ca.lo[5] = wv_lo;
    ca.src[6] = Wo;    ca.hi[6] = wo_hi;  ca.lo[6] = wo_lo;
    cvt_all<<<18432, 256>>>(ca);

    ProjArgs pa;
    pa.aq_hi = inq_hi; pa.aq_lo = inq_lo;
    pa.ak_hi = ink_hi; pa.ak_lo = ink_lo;
    pa.av_hi = inv_hi; pa.av_lo = inv_lo;
    pa.wq_hi = wq_hi; pa.wq_lo = wq_lo;
    pa.wk_hi = wk_hi; pa.wk_lo = wk_lo;
    pa.wv_hi = wv_hi; pa.wv_lo = wv_lo;
    pa.bq = bq; pa.bk = bk; pa.bv = bv;
    pa.q_hi = q_hi; pa.q_lo = q_lo;
    pa.k_hi = k_hi; pa.k_lo = k_lo;
    pa.vp_hi = vp_hi; pa.vp_lo = vp_lo;
    pa.kg = kg;
    pa.scale = 1.0f / sqrtf((float)QKD);
    proj_gemm<<<dim3(QKD / 128, NROWS / 128, 3), 128, GEMM_SMEM>>>(pa);

    corr_kernel<<<dim3(L_SEQ / 128, BATCH * NH), 256>>>(q_hi, q_lo, kg, corr);

    attn_mma<<<dim3(L_SEQ / 64, BATCH * NH), 128, ATTN_SMEM>>>(
        q_hi, q_lo, k_hi, k_lo, vp_hi, vp_lo, corr, at_hi, at_lo);

    out_gemm<<<dim3(EMB / 128, NROWS / 128), 128, GEMM_SMEM>>>(
        at_hi, at_lo, wo_hi, wo_lo, bo, out);
}

// round 16
// speedup vs baseline: 1.1247x; 1.0554x over previous
#include <cuda_runtime.h>
#include <cuda_bf16.h>
#include <stdint.h>
#include <math.h>

#define L_SEQ 2048
#define BATCH 2
#define EMB   1024
#define NH    16
#define DQKh  128
#define QKD   2048
#define DVh   64
#define NROWS 4096

typedef __nv_bfloat16 bf16;

// ---------------- scratch (static device globals; no allocation) -------------
__device__ bf16 g_inq_hi[(size_t)NROWS*EMB];
__device__ bf16 g_inq_lo[(size_t)NROWS*EMB];
__device__ bf16 g_ink_hi[(size_t)NROWS*EMB];
__device__ bf16 g_ink_lo[(size_t)NROWS*EMB];
__device__ bf16 g_inv_hi[(size_t)NROWS*EMB];
__device__ bf16 g_inv_lo[(size_t)NROWS*EMB];
__device__ bf16 g_wq_hi[(size_t)QKD*EMB];
__device__ bf16 g_wq_lo[(size_t)QKD*EMB];
__device__ bf16 g_wk_hi[(size_t)QKD*EMB];
__device__ bf16 g_wk_lo[(size_t)QKD*EMB];
__device__ bf16 g_wv_hi[(size_t)EMB*EMB];
__device__ bf16 g_wv_lo[(size_t)EMB*EMB];
__device__ bf16 g_wo_hi[(size_t)EMB*EMB];
__device__ bf16 g_wo_lo[(size_t)EMB*EMB];
__device__ bf16 g_q_hi[(size_t)BATCH*NH*L_SEQ*DQKh];
__device__ bf16 g_q_lo[(size_t)BATCH*NH*L_SEQ*DQKh];
__device__ bf16 g_k_hi[(size_t)BATCH*NH*L_SEQ*DQKh];   // pre-masked
__device__ bf16 g_k_lo[(size_t)BATCH*NH*L_SEQ*DQKh];   // pre-masked
__device__ uint32_t g_vp_hi[(size_t)BATCH*NH*(L_SEQ/2)*DVh]; // paired (s,s+1)
__device__ uint32_t g_vp_lo[(size_t)BATCH*NH*(L_SEQ/2)*DVh];
__device__ float g_kg[(size_t)BATCH*NH*32*DQKh];       // unmasked global k rows
__device__ bf16 g_at_hi[(size_t)NROWS*EMB];
__device__ bf16 g_at_lo[(size_t)NROWS*EMB];
__device__ float g_corr[(size_t)BATCH*NH*L_SEQ*32];
__device__ int   g_ws[NH*L_SEQ];

// ---------------- asm helpers -------------------------------------------------
__device__ __forceinline__ void mma_bf16(float c[4], const uint32_t a[4],
                                         uint32_t b0, uint32_t b1) {
    asm volatile(
        "mma.sync.aligned.m16n8k16.row.col.f32.bf16.bf16.f32 "
        "{%0,%1,%2,%3},{%4,%5,%6,%7},{%8,%9},{%0,%1,%2,%3};"
        : "+f"(c[0]), "+f"(c[1]), "+f"(c[2]), "+f"(c[3])
        : "r"(a[0]), "r"(a[1]), "r"(a[2]), "r"(a[3]), "r"(b0), "r"(b1));
}

#define CP16(dst, src) \
    asm volatile("cp.async.cg.shared.global [%0], [%1], 16;" \
                 :: "r"(dst), "l"(src))
#define CP_COMMIT() asm volatile("cp.async.commit_group;")
#define CP_WAIT1()  asm volatile("cp.async.wait_group 1;")
#define CP_WAIT0()  asm volatile("cp.async.wait_group 0;")

__device__ __forceinline__ uint32_t mpair(uint32_t v, int d, int ws) {
    uint32_t m = 0;
    if ((unsigned)(d - ws) < 32u)     m |= 0x0000FFFFu;
    if ((unsigned)(d + 1 - ws) < 32u) m |= 0xFFFF0000u;
    return v & m;
}

__device__ __forceinline__ void split_pack(float x, float y,
                                           uint32_t& hi, uint32_t& lo) {
    __nv_bfloat16 hx = __float2bfloat16(x), hy = __float2bfloat16(y);
    __nv_bfloat162 ph; ph.x = hx; ph.y = hy;
    hi = *(uint32_t*)&ph;
    __nv_bfloat162 pl;
    pl.x = __float2bfloat16(x - __bfloat162float(hx));
    pl.y = __float2bfloat16(y - __bfloat162float(hy));
    lo = *(uint32_t*)&pl;
}

__device__ __forceinline__ void store_hl(bf16* hip, bf16* lop, size_t idx,
                                         float v0, float v1) {
    __nv_bfloat16 h0 = __float2bfloat16(v0), h1 = __float2bfloat16(v1);
    __nv_bfloat162 hh; hh.x = h0; hh.y = h1;
    *(__nv_bfloat162*)(hip + idx) = hh;
    __nv_bfloat162 ll;
    ll.x = __float2bfloat16(v0 - __bfloat162float(h0));
    ll.y = __float2bfloat16(v1 - __bfloat162float(h1));
    *(__nv_bfloat162*)(lop + idx) = ll;
}

// ---------------- setup kernels ----------------------------------------------
__global__ void build_ws_kernel() {
    int idx = blockIdx.x * blockDim.x + threadIdx.x;
    if (idx >= NH * L_SEQ) return;
    int h = idx / L_SEQ, l = idx % L_SEQ;
    int ws = 0;
    if (h > 0) {
        int rn = 96 / h + 1;
        int i = l / rn, m = l % rn;
        int mm = (i & 1) ? (rn - 1 - m) : m;
        ws = mm * h;
    }
    g_ws[idx] = ws;
}

// one fused vectorized conversion of all 7 tensors (float4 per thread)
struct CvtArgs { const float* src[7]; bf16* hi[7]; bf16* lo[7]; };

__global__ void __launch_bounds__(256) cvt_all(CvtArgs a) {
    int t = blockIdx.x * 256 + threadIdx.x;   // float4 unit index
    int seg, j;
    if      (t < 1048576) { seg = 0; j = t; }
    else if (t < 2097152) { seg = 1; j = t - 1048576; }
    else if (t < 3145728) { seg = 2; j = t - 2097152; }
    else if (t < 3670016) { seg = 3; j = t - 3145728; }
    else if (t < 4194304) { seg = 4; j = t - 3670016; }
    else if (t < 4456448) { seg = 5; j = t - 4194304; }
    else                  { seg = 6; j = t - 4456448; }
    float4 x = ((const float4*)a.src[seg])[j];
    uint32_t h0, l0, h1, l1;
    split_pack(x.x, x.y, h0, l0);
    split_pack(x.z, x.w, h1, l1);
    ((uint2*)a.hi[seg])[j] = make_uint2(h0, h1);
    ((uint2*)a.lo[seg])[j] = make_uint2(l0, l1);
}

// ---------------- GEMM core: 128x128, 4 warps 64x64, cp.async x3, 1 barrier --
// MODE 0: fp32 out [M,N]
// MODE 1: relu*scale -> bf16 hi/lo planes [(b h) l d], D=128  (q, unmasked)
// MODE 2: linear -> DIRECT paired vp u32 planes (fused vpack)
// MODE 3: relu -> MASKED bf16 planes D=128 (k) + unmasked fp32 g_kg side rows
#define GSTAGE 24576

template <int MODE>
__device__ __forceinline__ void gemm_body(
    const bf16* __restrict__ Ahi, const bf16* __restrict__ Alo,
    const bf16* __restrict__ Whi, const bf16* __restrict__ Wlo,
    const float* __restrict__ bias,
    float* __restrict__ Cf, bf16* __restrict__ Ohi, bf16* __restrict__ Olo,
    float* __restrict__ kg,
    uint32_t* __restrict__ VPhi, uint32_t* __restrict__ VPlo,
    int N, int K, float scale)
{
    extern __shared__ bf16 gsm[];
    int tid = threadIdx.x;
    int wid = tid >> 5, lane = tid & 31;
    int r = lane >> 2, qc = lane & 3;
    int warp_m = (wid >> 1) * 64, warp_n = (wid & 1) * 64;
    int m0 = blockIdx.y * 128, n0 = blockIdx.x * 128;

    const bf16* pAh = Ahi + (size_t)m0 * K;
    const bf16* pAl = Alo + (size_t)m0 * K;
    const bf16* pWh = Whi + (size_t)n0 * K;
    const bf16* pWl = Wlo + (size_t)n0 * K;

    uint32_t sb = (uint32_t)__cvta_generic_to_shared(gsm);

    auto load_stage = [&](int kt, uint32_t sbase) {
        #pragma unroll
        for (int i = 0; i < 2; i++) {
            int c = tid + i * 128;
            int row = c >> 1, half = (c & 1) * 8;
            uint32_t dst = sbase + (uint32_t)(row * 24 + half) * 2;
            size_t off = (size_t)row * K + kt + half;
            CP16(dst,         pAh + off);
            CP16(dst +  6144, pAl + off);
            CP16(dst + 12288, pWh + off);
            CP16(dst + 18432, pWl + off);
        }
    };

    // 3-stage ring: prologue fills stages 0 and 1
    load_stage(0, sb);
    CP_COMMIT();
    load_stage(16, sb + GSTAGE);
    CP_COMMIT();

    float acc[4][8][4] = {};
    int T = K >> 4;
    int cur = 0, pf = 2;   // compute stage / prefetch stage indices (mod 3)
    for (int t = 0; t < T; t++) {
        if (t < T - 1) { CP_WAIT1(); } else { CP_WAIT0(); }
        __syncthreads();   // single barrier: stage t visible AND compute t-1 done
        if (t + 2 < T) { load_stage((t + 2) << 4, sb + pf * GSTAGE); CP_COMMIT(); }

        bf16* sAh = gsm + cur * (GSTAGE / 2);
        bf16* sAl = sAh + 3072;
        bf16* sWh = sAl + 3072;
        bf16* sWl = sWh + 3072;

        uint32_t af[2][4][4];
        #pragma unroll
        for (int mt = 0; mt < 4; mt++) {
            int row = warp_m + mt * 16 + r;
            af[0][mt][0] = *(const uint32_t*)&sAh[row * 24 + 2 * qc];
            af[0][mt][1] = *(const uint32_t*)&sAh[(row + 8) * 24 + 2 * qc];
            af[0][mt][2] = *(const uint32_t*)&sAh[row * 24 + 2 * qc + 8];
            af[0][mt][3] = *(const uint32_t*)&sAh[(row + 8) * 24 + 2 * qc + 8];
            af[1][mt][0] = *(const uint32_t*)&sAl[row * 24 + 2 * qc];
            af[1][mt][1] = *(const uint32_t*)&sAl[(row + 8) * 24 + 2 * qc];
            af[1][mt][2] = *(const uint32_t*)&sAl[row * 24 + 2 * qc + 8];
            af[1][mt][3] = *(const uint32_t*)&sAl[(row + 8) * 24 + 2 * qc + 8];
        }
        #pragma unroll
        for (int nt = 0; nt < 8; nt++) {
            int wrow = warp_n + nt * 8 + r;
            uint32_t bh0 = *(const uint32_t*)&sWh[wrow * 24 + 2 * qc];
            uint32_t bh1 = *(const uint32_t*)&sWh[wrow * 24 + 2 * qc + 8];
            uint32_t bl0 = *(const uint32_t*)&sWl[wrow * 24 + 2 * qc];
            uint32_t bl1 = *(const uint32_t*)&sWl[wrow * 24 + 2 * qc + 8];
            #pragma unroll
            for (int mt = 0; mt < 4; mt++) {
                mma_bf16(acc[mt][nt], af[0][mt], bh0, bh1);
                mma_bf16(acc[mt][nt], af[0][mt], bl0, bl1);
                mma_bf16(acc[mt][nt], af[1][mt], bh0, bh1);
            }
        }
        cur = (cur == 2) ? 0 : cur + 1;
        pf  = (pf == 2)  ? 0 : pf + 1;
    }

    if (MODE == 2) {
        // fused vpack: stage C-tile in smem, emit paired vp u32 planes directly.
        __syncthreads();   // all warps done reading the cp.async ring
        uint32_t* sHi = (uint32_t*)gsm;        // [128 rows][64 col-pairs] 32KB
        uint32_t* sLo = sHi + 128 * 64;        // 32KB (total 64KB <= 72KB ring)
        #pragma unroll
        for (int mt = 0; mt < 4; mt++) {
            #pragma unroll
            for (int nt = 0; nt < 8; nt++) {
                int rl0 = warp_m + mt * 16 + r;
                int rl1 = rl0 + 8;
                int cl  = warp_n + nt * 8 + 2 * qc;
                float b0f = bias[n0 + cl], b1f = bias[n0 + cl + 1];
                uint32_t h0, l0u, h1, l1u;
                split_pack(acc[mt][nt][0] + b0f, acc[mt][nt][1] + b1f, h0, l0u);
                split_pack(acc[mt][nt][2] + b0f, acc[mt][nt][3] + b1f, h1, l1u);
                int c2 = cl >> 1;
                sHi[rl0 * 64 + c2] = h0;  sHi[rl1 * 64 + c2] = h1;
                sLo[rl0 * 64 + c2] = l0u; sLo[rl1 * 64 + c2] = l1u;
            }
        }
        __syncthreads();
        int s2base = m0 >> 2;
        int hbase  = n0 >> 6;    // two heads per block
        #pragma unroll
        for (int it = 0; it < 32; it++) {
            int u = tid + it * 128;          // 4096 units: c2loc(64) x j(32) x b(2)
            int c2loc = u & 63;
            int j = (u >> 6) & 31;
            int b = u >> 11;
            int rA = 4 * j + b, rB = rA + 2;
            uint32_t hA = sHi[rA * 64 + c2loc], hB = sHi[rB * 64 + c2loc];
            uint32_t lA = sLo[rA * 64 + c2loc], lB = sLo[rB * 64 + c2loc];
            int hh = c2loc >> 5, d2 = c2loc & 31;
            int y = b * NH + hbase + hh;
            size_t o = ((size_t)y * (L_SEQ / 2) + s2base + j) * DVh + 2 * d2;
            *(uint2*)(VPhi + o) = make_uint2(__byte_perm(hA, hB, 0x5410),
                                             __byte_perm(hA, hB, 0x7632));
            *(uint2*)(VPlo + o) = make_uint2(__byte_perm(lA, lB, 0x5410),
                                             __byte_perm(lA, lB, 0x7632));
        }
        return;
    }

    #pragma unroll
    for (int mt = 0; mt < 4; mt++) {
        #pragma unroll
        for (int nt = 0; nt < 8; nt++) {
            int row0 = m0 + warp_m + mt * 16 + r;
            int row1 = row0 + 8;
            int col  = n0 + warp_n + nt * 8 + 2 * qc;
            float b0f = bias[col], b1f = bias[col + 1];
            float v00 = acc[mt][nt][0] + b0f, v01 = acc[mt][nt][1] + b1f;
            float v10 = acc[mt][nt][2] + b0f, v11 = acc[mt][nt][3] + b1f;
            if (MODE == 1 || MODE == 3) {
                v00 = fmaxf(v00, 0.f) * scale; v01 = fmaxf(v01, 0.f) * scale;
                v10 = fmaxf(v10, 0.f) * scale; v11 = fmaxf(v11, 0.f) * scale;
            }
            if (MODE == 0) {
                *(float2*)(Cf + (size_t)row0 * N + col) = make_float2(v00, v01);
                *(float2*)(Cf + (size_t)row1 * N + col) = make_float2(v10, v11);
            } else if (MODE == 1) {
                int h = col >> 7, d = col & 127;
                store_hl(Ohi, Olo,
                    ((size_t)((row0 & 1) * NH + h) * L_SEQ + (row0 >> 1)) * DQKh + d,
                    v00, v01);
                store_hl(Ohi, Olo,
                    ((size_t)((row1 & 1) * NH + h) * L_SEQ + (row1 >> 1)) * DQKh + d,
                    v10, v11);
            } else if (MODE == 3) {
                int h = col >> 7, d = col & 127;
                int l0i = row0 >> 1, b0i = row0 & 1;
                int l1i = row1 >> 1, b1i = row1 & 1;
                if (l0i < 16 || l0i >= L_SEQ - 16) {
                    int j = (l0i < 16) ? l0i : (l0i - (L_SEQ - 32));
                    size_t o = ((size_t)(b0i * NH + h) * 32 + j) * DQKh + d;
                    kg[o] = v00; kg[o + 1] = v01;
                }
                if (l1i < 16 || l1i >= L_SEQ - 16) {
                    int j = (l1i < 16) ? l1i : (l1i - (L_SEQ - 32));
                    size_t o = ((size_t)(b1i * NH + h) * 32 + j) * DQKh + d;
                    kg[o] = v10; kg[o + 1] = v11;
                }
                if (h != 0) {
                    int ws0 = g_ws[h * L_SEQ + l0i];
                    int ws1 = g_ws[h * L_SEQ + l1i];
                    if ((unsigned)(d - ws0) >= 32u)     v00 = 0.f;
                    if ((unsigned)(d + 1 - ws0) >= 32u) v01 = 0.f;
                    if ((unsigned)(d - ws1) >= 32u)     v10 = 0.f;
                    if ((unsigned)(d + 1 - ws1) >= 32u) v11 = 0.f;
                }
                store_hl(Ohi, Olo,
                    ((size_t)(b0i * NH + h) * L_SEQ + l0i) * DQKh + d, v00, v01);
                store_hl(Ohi, Olo,
                    ((size_t)(b1i * NH + h) * L_SEQ + l1i) * DQKh + d, v10, v11);
            }
        }
    }
}

// fused q/k/v projection: z=0 -> q (MODE1), z=1 -> k (MODE3), z=2 -> v (MODE2)
struct ProjArgs {
    const bf16 *aq_hi, *aq_lo, *ak_hi, *ak_lo, *av_hi, *av_lo;
    const bf16 *wq_hi, *wq_lo, *wk_hi, *wk_lo, *wv_hi, *wv_lo;
    const float *bq, *bk, *bv;
    bf16 *q_hi, *q_lo, *k_hi, *k_lo;
    uint32_t *vp_hi, *vp_lo;
    float* kg;
    float scale;
};

__global__ void __launch_bounds__(128) proj_gemm(ProjArgs p) {
    int z = blockIdx.z;
    if (z == 0) {
        gemm_body<1>(p.aq_hi, p.aq_lo, p.wq_hi, p.wq_lo, p.bq,
                     nullptr, p.q_hi, p.q_lo, nullptr, nullptr, nullptr,
                     QKD, EMB, p.scale);
    } else if (z == 1) {
        gemm_body<3>(p.ak_hi, p.ak_lo, p.wk_hi, p.wk_lo, p.bk,
                     nullptr, p.k_hi, p.k_lo, p.kg, nullptr, nullptr,
                     QKD, EMB, 1.0f);
    } else {
        if (blockIdx.x >= EMB / 128) return;
        gemm_body<2>(p.av_hi, p.av_lo, p.wv_hi, p.wv_lo, p.bv,
                     nullptr, nullptr, nullptr, nullptr, p.vp_hi, p.vp_lo,
                     EMB, EMB, 1.0f);
    }
}

__global__ void __launch_bounds__(128) out_gemm(
    const bf16* __restrict__ Ahi, const bf16* __restrict__ Alo,
    const bf16* __restrict__ Whi, const bf16* __restrict__ Wlo,
    const float* __restrict__ bias, float* __restrict__ Cf)
{
    gemm_body<0>(Ahi, Alo, Whi, Wlo, bias, Cf, nullptr, nullptr, nullptr,
                 nullptr, nullptr, EMB, EMB, 1.0f);
}

// ---------------- corr via MMA: corr[y,l,j] = q[l]·kg[j] ---------------------
// grid (L_SEQ/128, B*NH), 128 threads (4 warps x 32 l-rows). 3-term split.
__global__ void __launch_bounds__(128) corr_mma(
    const bf16* __restrict__ qhi, const bf16* __restrict__ qlo,
    const float* __restrict__ kg, float* __restrict__ corr)
{
    __shared__ bf16 sgh[32 * 136];
    __shared__ bf16 sgl[32 * 136];
    int tid = threadIdx.x;
    int wid = tid >> 5, lane = tid & 31;
    int r = lane >> 2, qc = lane & 3;
    int y = blockIdx.y;
    int l0 = blockIdx.x * 128;

    // load kg (32x128 fp32) -> bf16 hi/lo smem tiles, K-tile layout (stride 136)
    for (int i = tid; i < 32 * 128; i += 128) {
        int j = i >> 7, d = i & 127;
        float x = kg[(size_t)y * 32 * 128 + i];
        bf16 hh = __float2bfloat16(x);
        sgh[j * 136 + d] = hh;
        sgl[j * 136 + d] = __float2bfloat16(x - __bfloat162float(hh));
    }
    __syncthreads();

    float acc[2][4][4] = {};
    #pragma unroll
    for (int mt = 0; mt < 2; mt++) {
        size_t rb0 = ((size_t)y * L_SEQ + l0 + wid * 32 + mt * 16 + r) * DQKh;
        size_t rb1 = rb0 + 8 * DQKh;
        #pragma unroll
        for (int ks = 0; ks < 8; ks++) {
            int d0 = ks * 16 + 2 * qc;
            int d2 = d0 + 8;
            uint32_t ah[4], al[4];
            ah[0] = *(const uint32_t*)(qhi + rb0 + d0);
            ah[1] = *(const uint32_t*)(qhi + rb1 + d0);
            ah[2] = *(const uint32_t*)(qhi + rb0 + d2);
            ah[3] = *(const uint32_t*)(qhi + rb1 + d2);
            al[0] = *(const uint32_t*)(qlo + rb0 + d0);
            al[1] = *(const uint32_t*)(qlo + rb1 + d0);
            al[2] = *(const uint32_t*)(qlo + rb0 + d2);
            al[3] = *(const uint32_t*)(qlo + rb1 + d2);
            #pragma unroll
            for (int nt = 0; nt < 4; nt++) {
                int so = (nt * 8 + r) * 136 + ks * 16 + 2 * qc;
                uint32_t bh0 = *(const uint32_t*)&sgh[so];
                uint32_t bh1 = *(const uint32_t*)&sgh[so + 8];
                uint32_t bl0 = *(const uint32_t*)&sgl[so];
                uint32_t bl1 = *(const uint32_t*)&sgl[so + 8];
                mma_bf16(acc[mt][nt], ah, bh0, bh1);
                mma_bf16(acc[mt][nt], ah, bl0, bl1);
                mma_bf16(acc[mt][nt], al, bh0, bh1);
            }
        }
    }

    #pragma unroll
    for (int mt = 0; mt < 2; mt++) {
        int lrow0 = l0 + wid * 32 + mt * 16 + r;
        #pragma unroll
        for (int nt = 0; nt < 4; nt++) {
            int col = nt * 8 + 2 * qc;
            *(float2*)(corr + ((size_t)y * L_SEQ + lrow0) * 32 + col) =
                make_float2(acc[mt][nt][0], acc[mt][nt][1]);
            *(float2*)(corr + ((size_t)y * L_SEQ + lrow0 + 8) * 32 + col) =
                make_float2(acc[mt][nt][2], acc[mt][nt][3]);
        }
    }
}

// ---------------- attention: 128 thr, 64 q-rows, cp.async x2, 1 barrier ------
#define AT_KHI 0
#define AT_KLO 17408
#define AT_VHI 34816
#define AT_VLO 44032
#define AT_STAGE 53248

__global__ void __launch_bounds__(128) attn_mma(
    const bf16* __restrict__ qhi, const bf16* __restrict__ qlo,
    const bf16* __restrict__ khi, const bf16* __restrict__ klo,
    const uint32_t* __restrict__ vphi, const uint32_t* __restrict__ vplo,
    const float* __restrict__ corr,
    bf16* __restrict__ ohi, bf16* __restrict__ olo)
{
    extern __shared__ uint8_t sraw[];
    int tid = threadIdx.x;
    int wid = tid >> 5, lane = tid & 31;
    int r = lane >> 2, qc = lane & 3;
    int y = blockIdx.y;
    int h = y & 15;
    int l0 = blockIdx.x * 64;
    int lr = l0 + wid * 16 + r;

    uint32_t sb = (uint32_t)__cvta_generic_to_shared(sraw);

    auto load_stage = [&](int st, uint32_t sbase) {
        int s0 = st * 64;
        size_t kbase = ((size_t)y * L_SEQ + s0) * DQKh;
        #pragma unroll
        for (int i = 0; i < 8; i++) {
            int c = tid + i * 128;
            int row = c >> 4, ch = (c & 15) * 8;
            uint32_t dst = sbase + (uint32_t)(row * 272 + ch * 2);
            CP16(dst + AT_KHI, khi + kbase + row * 128 + ch);
            CP16(dst + AT_KLO, klo + kbase + row * 128 + ch);
        }
        size_t vbase = ((size_t)y * (L_SEQ / 2) + st * 32) * DVh;
        #pragma unroll
        for (int i = 0; i < 4; i++) {
            int c = tid + i * 128;
            int s2 = c >> 4, ch = (c & 15) * 4;
            uint32_t dst = sbase + (uint32_t)(s2 * 288 + ch * 4);
            CP16(dst + AT_VHI, vphi + vbase + s2 * 64 + ch);
            CP16(dst + AT_VLO, vplo + vbase + s2 * 64 + ch);
        }
    };

    // masked Q fragments in registers
    uint32_t qa[8][2][4];
    {
        size_t rb0 = ((size_t)y * L_SEQ + lr) * DQKh;
        size_t rb1 = rb0 + 8 * DQKh;
        int ws0 = (h == 0) ? 0 : g_ws[h * L_SEQ + lr];
        int ws1 = (h == 0) ? 0 : g_ws[h * L_SEQ + lr + 8];
        #pragma unroll
        for (int ks = 0; ks < 8; ks++) {
            int d0 = ks * 16 + 2 * qc;
            int d2 = d0 + 8;
            uint32_t a0 = *(const uint32_t*)(qhi + rb0 + d0);
            uint32_t a1 = *(const uint32_t*)(qhi + rb1 + d0);
            uint32_t a2 = *(const uint32_t*)(qhi + rb0 + d2);
            uint32_t a3 = *(const uint32_t*)(qhi + rb1 + d2);
            uint32_t c0 = *(const uint32_t*)(qlo + rb0 + d0);
            uint32_t c1 = *(const uint32_t*)(qlo + rb1 + d0);
            uint32_t c2 = *(const uint32_t*)(qlo + rb0 + d2);
            uint32_t c3 = *(const uint32_t*)(qlo + rb1 + d2);
            if (h != 0) {
                a0 = mpair(a0, d0, ws0); a1 = mpair(a1, d0, ws1);
                a2 = mpair(a2, d2, ws0); a3 = mpair(a3, d2, ws1);
                c0 = mpair(c0, d0, ws0); c1 = mpair(c1, d0, ws1);
                c2 = mpair(c2, d2, ws0); c3 = mpair(c3, d2, ws1);
            }
            qa[ks][0][0] = a0; qa[ks][0][1] = a1;
            qa[ks][0][2] = a2; qa[ks][0][3] = a3;
            qa[ks][1][0] = c0; qa[ks][1][1] = c1;
            qa[ks][1][2] = c2; qa[ks][1][3] = c3;
        }
    }

    load_stage(0, sb);
    CP_COMMIT();

    float oacc[8][4] = {};
    float den0 = 0.f, den1 = 0.f;

    for (int st = 0; st < 32; st++) {
        CP_WAIT0();
        __syncthreads();
        if (st + 1 < 32) { load_stage(st + 1, sb + ((st + 1) & 1) * AT_STAGE); CP_COMMIT(); }

        uint8_t* stg = sraw + (st & 1) * AT_STAGE;
        bf16* sKhi = (bf16*)(stg + AT_KHI);
        bf16* sKlo = (bf16*)(stg + AT_KLO);
        uint32_t* sVhiP = (uint32_t*)(stg + AT_VHI);
        uint32_t* sVloP = (uint32_t*)(stg + AT_VLO);

        // S = Qmasked @ Kmasked^T (3-term split)
        float sacc[8][4] = {};
        #pragma unroll
        for (int ks = 0; ks < 8; ks++) {
            #pragma unroll
            for (int nt = 0; nt < 8; nt++) {
                int so = (nt * 8 + r) * 136 + ks * 16 + 2 * qc;
                uint32_t bh0 = *(const uint32_t*)&sKhi[so];
                uint32_t bh1 = *(const uint32_t*)&sKhi[so + 8];
                uint32_t bl0 = *(const uint32_t*)&sKlo[so];
                uint32_t bl1 = *(const uint32_t*)&sKlo[so + 8];
                mma_bf16(sacc[nt], qa[ks][0], bh0, bh1);
                mma_bf16(sacc[nt], qa[ks][0], bl0, bl1);
                mma_bf16(sacc[nt], qa[ks][1], bh0, bh1);
            }
        }

        // global-key correction
        if (st == 0) {
            #pragma unroll
            for (int nt = 0; nt < 2; nt++) {
                size_t c0i = ((size_t)y * L_SEQ + lr) * 32 + nt * 8 + 2 * qc;
                size_t c1i = c0i + 8 * 32;
                sacc[nt][0] += corr[c0i]; sacc[nt][1] += corr[c0i + 1];
                sacc[nt][2] += corr[c1i]; sacc[nt][3] += corr[c1i + 1];
            }
        } else if (st == 31) {
            #pragma unroll
            for (int i2 = 0; i2 < 2; i2++) {
                int nt = 6 + i2;
                size_t c0i = ((size_t)y * L_SEQ + lr) * 32 + 16 + i2 * 8 + 2 * qc;
                size_t c1i = c0i + 8 * 32;
                sacc[nt][0] += corr[c0i]; sacc[nt][1] += corr[c0i + 1];
                sacc[nt][2] += corr[c1i]; sacc[nt][3] += corr[c1i + 1];
            }
        }

        // denominator partials
        #pragma unroll
        for (int nt = 0; nt < 8; nt++) {
            den0 += sacc[nt][0] + sacc[nt][1];
            den1 += sacc[nt][2] + sacc[nt][3];
        }

        // O += S @ V (S frags re-split to bf16 as A fragments)
        #pragma unroll
        for (int kk = 0; kk < 4; kk++) {
            uint32_t ahi[4], alo[4];
            split_pack(sacc[2 * kk][0],     sacc[2 * kk][1],     ahi[0], alo[0]);
            split_pack(sacc[2 * kk][2],     sacc[2 * kk][3],     ahi[1], alo[1]);
            split_pack(sacc[2 * kk + 1][0], sacc[2 * kk + 1][1], ahi[2], alo[2]);
            split_pack(sacc[2 * kk + 1][2], sacc[2 * kk + 1][3], ahi[3], alo[3]);
            #pragma unroll
            for (int nt = 0; nt < 8; nt++) {
                int vo = (kk * 8 + qc) * 72 + nt * 8 + r;
                uint32_t bh0 = sVhiP[vo], bh1 = sVhiP[vo + 4 * 72];
                uint32_t bl0 = sVloP[vo], bl1 = sVloP[vo + 4 * 72];
                mma_bf16(oacc[nt], ahi, bh0, bh1);
                mma_bf16(oacc[nt], ahi, bl0, bl1);
                mma_bf16(oacc[nt], alo, bh0, bh1);
            }
        }
    }

    den0 += __shfl_xor_sync(0xffffffffu, den0, 1);
    den0 += __shfl_xor_sync(0xffffffffu, den0, 2);
    den1 += __shfl_xor_sync(0xffffffffu, den1, 1);
    den1 += __shfl_xor_sync(0xffffffffu, den1, 2);
    float inv0 = 1.0f / fmaxf(den0, 1e-12f);
    float inv1 = 1.0f / fmaxf(den1, 1e-12f);

    int b = y >> 4;
    int row0 = (lr)     * BATCH + b;
    int row1 = (lr + 8) * BATCH + b;
    #pragma unroll
    for (int nt = 0; nt < 8; nt++) {
        int d = h * DVh + nt * 8 + 2 * qc;
        store_hl(ohi, olo, (size_t)row0 * EMB + d,
                 oacc[nt][0] * inv0, oacc[nt][1] * inv0);
        store_hl(ohi, olo, (size_t)row1 * EMB + d,
                 oacc[nt][2] * inv1, oacc[nt][3] * inv1);
    }
}

// ---------------- launch ------------------------------------------------------
extern "C" void kernel_launch(void* const* d_in, const int* in_sizes, int n_in,
                              void* d_out, int out_size)
{
    (void)in_sizes; (void)n_in; (void)out_size;
    const float* query = (const float*)d_in[0];
    const float* key_  = (const float*)d_in[1];
    const float* value = (const float*)d_in[2];
    const float* Wq    = (const float*)d_in[3];
    const float* bq    = (const float*)d_in[4];
    const float* Wk    = (const float*)d_in[5];
    const float* bk    = (const float*)d_in[6];
    const float* Wv    = (const float*)d_in[7];
    const float* bv    = (const float*)d_in[8];
    const float* Wo    = (const float*)d_in[9];
    const float* bo    = (const float*)d_in[10];
    float* out = (float*)d_out;

    bf16 *inq_hi,*inq_lo,*ink_hi,*ink_lo,*inv_hi,*inv_lo;
    bf16 *wq_hi,*wq_lo,*wk_hi,*wk_lo,*wv_hi,*wv_lo,*wo_hi,*wo_lo;
    bf16 *q_hi,*q_lo,*k_hi,*k_lo,*at_hi,*at_lo;
    uint32_t *vp_hi,*vp_lo;
    float *corr,*kg;
    cudaGetSymbolAddress((void**)&inq_hi, g_inq_hi);
    cudaGetSymbolAddress((void**)&inq_lo, g_inq_lo);
    cudaGetSymbolAddress((void**)&ink_hi, g_ink_hi);
    cudaGetSymbolAddress((void**)&ink_lo, g_ink_lo);
    cudaGetSymbolAddress((void**)&inv_hi, g_inv_hi);
    cudaGetSymbolAddress((void**)&inv_lo, g_inv_lo);
    cudaGetSymbolAddress((void**)&wq_hi, g_wq_hi);
    cudaGetSymbolAddress((void**)&wq_lo, g_wq_lo);
    cudaGetSymbolAddress((void**)&wk_hi, g_wk_hi);
    cudaGetSymbolAddress((void**)&wk_lo, g_wk_lo);
    cudaGetSymbolAddress((void**)&wv_hi, g_wv_hi);
    cudaGetSymbolAddress((void**)&wv_lo, g_wv_lo);
    cudaGetSymbolAddress((void**)&wo_hi, g_wo_hi);
    cudaGetSymbolAddress((void**)&wo_lo, g_wo_lo);
    cudaGetSymbolAddress((void**)&q_hi, g_q_hi);
    cudaGetSymbolAddress((void**)&q_lo, g_q_lo);
    cudaGetSymbolAddress((void**)&k_hi, g_k_hi);
    cudaGetSymbolAddress((void**)&k_lo, g_k_lo);
    cudaGetSymbolAddress((void**)&vp_hi, g_vp_hi);
    cudaGetSymbolAddress((void**)&vp_lo, g_vp_lo);
    cudaGetSymbolAddress((void**)&at_hi, g_at_hi);
    cudaGetSymbolAddress((void**)&at_lo, g_at_lo);
    cudaGetSymbolAddress((void**)&corr, g_corr);
    cudaGetSymbolAddress((void**)&kg, g_kg);

    const int GEMM_SMEM = 3 * GSTAGE;   // 73728
    cudaFuncSetAttribute(proj_gemm, cudaFuncAttributeMaxDynamicSharedMemorySize, GEMM_SMEM);
    cudaFuncSetAttribute(out_gemm,  cudaFuncAttributeMaxDynamicSharedMemorySize, GEMM_SMEM);
    const int ATTN_SMEM = 2 * AT_STAGE;
    cudaFuncSetAttribute(attn_mma, cudaFuncAttributeMaxDynamicSharedMemorySize, ATTN_SMEM);

    build_ws_kernel<<<(NH * L_SEQ + 255) / 256, 256>>>();

    CvtArgs ca;
    ca.src[0] = query; ca.hi[0] = inq_hi; ca.lo[0] = inq_lo;
    ca.src[1] = key_;  ca.hi[1] = ink_hi; ca.lo[1] = ink_lo;
    ca.src[2] = value; ca.hi[2] = inv_hi; ca.lo[2] = inv_lo;
    ca.src[3] = Wq;    ca.hi[3] = wq_hi;  ca.lo[3] = wq_lo;
    ca.src[4] = Wk;    ca.hi[4] = wk_hi;  ca.lo[4] = wk_lo;
    ca.src[5] = Wv;    ca.hi[5] = wv_hi;  ca.lo[5] = wv_lo;
    ca.src[6] = Wo;    ca.hi[6] = wo_hi;  ca.lo[6] = wo_lo;
    cvt_all<<<18432, 256>>>(ca);

    ProjArgs pa;
    pa.aq_hi = inq_hi; pa.aq_lo = inq_lo;
    pa.ak_hi = ink_hi; pa.ak_lo = ink_lo;
    pa.av_hi = inv_hi; pa.av_lo = inv_lo;
    pa.wq_hi = wq_hi; pa.wq_lo = wq_lo;
    pa.wk_hi = wk_hi; pa.wk_lo = wk_lo;
    pa.wv_hi = wv_hi; pa.wv_lo = wv_lo;
    pa.bq = bq; pa.bk = bk; pa.bv = bv;
    pa.q_hi = q_hi; pa.q_lo = q_lo;
    pa.k_hi = k_hi; pa.k_lo = k_lo;
    pa.vp_hi = vp_hi; pa.vp_lo = vp_lo;
    pa.kg = kg;
    pa.scale = 1.0f / sqrtf((float)QKD);
    proj_gemm<<<dim3(QKD / 128, NROWS / 128, 3), 128, GEMM_SMEM>>>(pa);

    corr_mma<<<dim3(L_SEQ / 128, BATCH * NH), 128>>>(q_hi, q_lo, kg, corr);

    attn_mma<<<dim3(L_SEQ / 64, BATCH * NH), 128, ATTN_SMEM>>>(
        q_hi, q_lo, k_hi, k_lo, vp_hi, vp_lo, corr, at_hi, at_lo);

    out_gemm<<<dim3(EMB / 128, NROWS / 128), 128, GEMM_SMEM>>>(
        at_hi, at_lo, wo_hi, wo_lo, bo, out);
}